// round 7
// baseline (speedup 1.0000x reference)
#include <cuda_runtime.h>
#include <math.h>
#include <stdint.h>

// Problem dims
#define Q    64
#define SQ   32
#define CC   256
#define SC   256
#define H    768
#define D    128
#define QT   31
#define CT   255
#define QROWS (Q*QT)     // 1984
#define CROWS (CC*CT)    // 65280
#define NROWS (QROWS+CROWS)

// Scratch
__device__ float g_col[(size_t)NROWS * D];
__device__ float g_denom[Q];
__device__ int   g_idx[CC * 256];   // per-doc compacted token indices (0-based in doc)
__device__ int   g_cnt[CC];         // per-doc compact count (unmasked + 1 masked rep)

// ---------------------------------------------------------------------------
// helpers
// ---------------------------------------------------------------------------
__device__ __forceinline__ float f2tf(float x) {
    uint32_t r;
    asm("cvt.rna.tf32.f32 %0, %1;" : "=r"(r) : "f"(x));
    return __uint_as_float(r);
}
__device__ __forceinline__ void mma_tf32(float* c, const uint32_t* a, const uint32_t* b) {
    asm volatile(
        "mma.sync.aligned.m16n8k8.row.col.f32.tf32.tf32.f32 "
        "{%0,%1,%2,%3},{%4,%5,%6,%7},{%8,%9},{%0,%1,%2,%3};\n"
        : "+f"(c[0]), "+f"(c[1]), "+f"(c[2]), "+f"(c[3])
        : "r"(a[0]), "r"(a[1]), "r"(a[2]), "r"(a[3]), "r"(b[0]), "r"(b[1]));
}
__device__ __forceinline__ uint32_t smem_u32(const void* p) {
    uint32_t a;
    asm("{ .reg .u64 t; cvta.to.shared.u64 t, %1; cvt.u32.u64 %0, t; }" : "=r"(a) : "l"(p));
    return a;
}
#define CP_ASYNC16(dst_u32, src_ptr) \
    asm volatile("cp.async.ca.shared.global [%0], [%1], 16;" :: "r"(dst_u32), "l"(src_ptr))
#define CP_COMMIT() asm volatile("cp.async.commit_group;" ::: "memory")
#define CP_WAIT1()  asm volatile("cp.async.wait_group 1;" ::: "memory")
#define CP_WAIT0()  asm volatile("cp.async.wait_group 0;" ::: "memory")

// ---------------------------------------------------------------------------
// Kernel 1: pooled vectors (fp32 exact)
// ---------------------------------------------------------------------------
__global__ void pooled_kernel(const float* __restrict__ qh,
                              const float* __restrict__ ch,
                              const int*   __restrict__ qm,
                              const int*   __restrict__ cm,
                              float* __restrict__ out) {
    int r = blockIdx.x;
    const float* src;
    float mask;
    float* dst;
    if (r < Q) {
        src  = qh + (size_t)r * SQ * H;
        mask = (float)qm[r * SQ];
        dst  = out + Q * CC + (size_t)r * H;
    } else {
        int c = r - Q;
        src  = ch + (size_t)c * SC * H;
        mask = (float)cm[c * SC];
        dst  = out + Q * CC + Q * H + (size_t)c * H;
    }
    __shared__ float red[8];
    int t = threadIdx.x;
    float v[3];
    float s = 0.f;
#pragma unroll
    for (int it = 0; it < 3; it++) {
        float x = src[t + it * 256] * mask;
        v[it] = x;
        s += x * x;
    }
#pragma unroll
    for (int o = 16; o; o >>= 1) s += __shfl_xor_sync(0xffffffffu, s, o);
    if ((t & 31) == 0) red[t >> 5] = s;
    __syncthreads();
    if (t < 8) {
        float ss = red[t];
#pragma unroll
        for (int o = 4; o; o >>= 1) ss += __shfl_xor_sync(0xffu, ss, o);
        if (t == 0) red[0] = ss;
    }
    __syncthreads();
    float inv = 1.f / fmaxf(sqrtf(red[0]), 1e-12f);
#pragma unroll
    for (int it = 0; it < 3; it++) dst[t + it * 256] = v[it] * inv;
}

// ---------------------------------------------------------------------------
// Kernel 2: denominators
// ---------------------------------------------------------------------------
__global__ void denom_kernel(const int* __restrict__ qm) {
    int q = threadIdx.x;
    if (q < Q) {
        int s = 0;
        for (int i = 1; i < SQ; i++) s += qm[q * SQ + i];
        g_denom[q] = (float)s;
    }
}

// ---------------------------------------------------------------------------
// Kernel 2b: per-doc token compaction.
// idx list = all unmasked tokens + ONE masked representative (all masked
// tokens share the identical projected column, so one suffices for the max).
// 256 blocks x 256 threads; thread t handles token t (tokens 1..255).
// ---------------------------------------------------------------------------
__global__ void compact_kernel(const int* __restrict__ cm) {
    int c = blockIdx.x, t = threadIdx.x;
    __shared__ int wcnt[8];
    __shared__ int firstmask;
    if (t == 0) firstmask = 1 << 30;
    __syncthreads();
    int valid = (t >= 1);
    int m = valid ? cm[c * SC + t] : 0;
    unsigned bal = __ballot_sync(0xffffffffu, m != 0);
    int w = t >> 5, lane = t & 31;
    int pre = __popc(bal & ((1u << lane) - 1));
    if (lane == 0) wcnt[w] = __popc(bal);
    if (valid && !m) atomicMin(&firstmask, t);
    __syncthreads();
    int off = 0;
    for (int i = 0; i < w; i++) off += wcnt[i];
    if (valid && m) g_idx[c * 256 + off + pre] = t - 1;   // 0-based row in doc
    if (t == 0) {
        int total = 0;
        for (int i = 0; i < 8; i++) total += wcnt[i];
        if (firstmask < 256) { g_idx[c * 256 + total] = firstmask - 1; total++; }
        g_cnt[c] = total;
    }
}

// ---------------------------------------------------------------------------
// Kernel 3: projection + l2norm (unchanged — at its mma.sync tf32 floor)
// ---------------------------------------------------------------------------
#define P_SA 36
#define P_SW 132
__global__ __launch_bounds__(256) void proj_kernel(const float* __restrict__ qh,
                                                   const float* __restrict__ ch,
                                                   const float* __restrict__ Wm,
                                                   const float* __restrict__ bias,
                                                   const int*   __restrict__ qm,
                                                   const int*   __restrict__ cm) {
    __shared__ float As[2][64 * P_SA];
    __shared__ float Ws[2][32 * P_SW];
    __shared__ float rowsq[64][4];
    __shared__ float invn[64];
    __shared__ const float* srcp[64];
    __shared__ float mk[64];

    int t = threadIdx.x;
    int w = t >> 5, lane = t & 31, g = lane >> 2, tg = lane & 3;
    int mw = w & 1, nw = w >> 1;
    int m_warp = mw * 32, n_warp = nw * 32;

    if (t < 64) {
        int r = blockIdx.x * 64 + t;
        if (r < QROWS) {
            int q = r / QT, i = r - q * QT;
            srcp[t] = qh + (size_t)(q * SQ + i + 1) * H;
            mk[t]   = (float)qm[q * SQ + i + 1];
        } else {
            int rc = r - QROWS;
            int c = rc / CT, j = rc - c * CT;
            srcp[t] = ch + (size_t)(c * SC + j + 1) * H;
            mk[t]   = (float)cm[c * SC + j + 1];
        }
    }

    float binit[4][2];
#pragma unroll
    for (int nt4 = 0; nt4 < 4; nt4++) {
        int col = n_warp + nt4 * 8 + 2 * tg;
        binit[nt4][0] = bias[col];
        binit[nt4][1] = bias[col + 1];
    }
    __syncthreads();

    uint32_t sA0 = smem_u32(&As[0][0]), sA1 = smem_u32(&As[1][0]);
    uint32_t sW0 = smem_u32(&Ws[0][0]), sW1 = smem_u32(&Ws[1][0]);

#define STAGE(bufA, bufW, KT) do {                                              \
    _Pragma("unroll")                                                           \
    for (int itc = 0; itc < 2; itc++) {                                         \
        int idx = t + itc * 256;                                                \
        int m = idx >> 3, k4 = idx & 7;                                         \
        CP_ASYNC16((bufA) + (m * P_SA + k4 * 4) * 4, srcp[m] + (KT) + k4 * 4);  \
    }                                                                           \
    _Pragma("unroll")                                                           \
    for (int itc = 0; itc < 4; itc++) {                                         \
        int idx = t + itc * 256;                                                \
        int k = idx >> 5, d4 = idx & 31;                                        \
        CP_ASYNC16((bufW) + (k * P_SW + d4 * 4) * 4,                            \
                   Wm + (size_t)((KT) + k) * D + d4 * 4);                       \
    }                                                                           \
} while (0)

    STAGE(sA0, sW0, 0);
    CP_COMMIT();

    float acc[2][4][4];
#pragma unroll
    for (int mt = 0; mt < 2; mt++)
#pragma unroll
        for (int nt4 = 0; nt4 < 4; nt4++)
#pragma unroll
            for (int i = 0; i < 4; i++) acc[mt][nt4][i] = 0.f;

    for (int it = 0; it < 24; it++) {
        if (it < 23) {
            if (it & 1) STAGE(sA0, sW0, (it + 1) * 32);
            else        STAGE(sA1, sW1, (it + 1) * 32);
            CP_COMMIT();
            CP_WAIT1();
        } else {
            CP_WAIT0();
        }
        __syncthreads();
        const float* A = As[it & 1];
        const float* W = Ws[it & 1];
#pragma unroll
        for (int ks = 0; ks < 4; ks++) {
            int k0 = ks * 8;
            uint32_t afr[2][4], bfr[4][2];
#pragma unroll
            for (int mt = 0; mt < 2; mt++) {
                int base = m_warp + mt * 16;
                afr[mt][0] = __float_as_uint(A[(base + g)     * P_SA + k0 + tg]);
                afr[mt][1] = __float_as_uint(A[(base + g + 8) * P_SA + k0 + tg]);
                afr[mt][2] = __float_as_uint(A[(base + g)     * P_SA + k0 + tg + 4]);
                afr[mt][3] = __float_as_uint(A[(base + g + 8) * P_SA + k0 + tg + 4]);
            }
#pragma unroll
            for (int nt4 = 0; nt4 < 4; nt4++) {
                int col = n_warp + nt4 * 8 + g;
                bfr[nt4][0] = __float_as_uint(W[(k0 + tg)     * P_SW + col]);
                bfr[nt4][1] = __float_as_uint(W[(k0 + tg + 4) * P_SW + col]);
            }
#pragma unroll
            for (int mt = 0; mt < 2; mt++)
#pragma unroll
                for (int nt4 = 0; nt4 < 4; nt4++)
                    mma_tf32(acc[mt][nt4], afr[mt], bfr[nt4]);
        }
        __syncthreads();
    }

    float mrow[2][2];
#pragma unroll
    for (int mt = 0; mt < 2; mt++) {
        mrow[mt][0] = mk[m_warp + mt * 16 + g];
        mrow[mt][1] = mk[m_warp + mt * 16 + g + 8];
    }
#pragma unroll
    for (int mt = 0; mt < 2; mt++)
#pragma unroll
        for (int nt4 = 0; nt4 < 4; nt4++)
#pragma unroll
            for (int i = 0; i < 4; i++)
                acc[mt][nt4][i] = mrow[mt][i >> 1] * acc[mt][nt4][i] + binit[nt4][i & 1];

    float pr[2][2];
#pragma unroll
    for (int mt = 0; mt < 2; mt++)
#pragma unroll
        for (int h = 0; h < 2; h++) {
            float s = 0.f;
#pragma unroll
            for (int nt4 = 0; nt4 < 4; nt4++) {
                float c0 = acc[mt][nt4][2 * h], c1 = acc[mt][nt4][2 * h + 1];
                s += c0 * c0 + c1 * c1;
            }
            pr[mt][h] = s;
        }
#pragma unroll
    for (int off = 1; off <= 2; off <<= 1) {
#pragma unroll
        for (int mt = 0; mt < 2; mt++)
#pragma unroll
            for (int h = 0; h < 2; h++)
                pr[mt][h] += __shfl_xor_sync(0xffffffffu, pr[mt][h], off);
    }
    if (tg == 0) {
#pragma unroll
        for (int mt = 0; mt < 2; mt++)
#pragma unroll
            for (int h = 0; h < 2; h++)
                rowsq[m_warp + mt * 16 + g + 8 * h][nw] = pr[mt][h];
    }
    __syncthreads();
    if (t < 64) {
        float s = rowsq[t][0] + rowsq[t][1] + rowsq[t][2] + rowsq[t][3];
        invn[t] = 1.f / fmaxf(sqrtf(s), 1e-12f);
    }
    __syncthreads();

    size_t gbase = (size_t)blockIdx.x * 64;
#pragma unroll
    for (int mt = 0; mt < 2; mt++)
#pragma unroll
        for (int h = 0; h < 2; h++) {
            int r = m_warp + mt * 16 + g + 8 * h;
            float inv = invn[r];
            float* dst = g_col + (gbase + r) * D;
#pragma unroll
            for (int nt4 = 0; nt4 < 4; nt4++) {
                int col = n_warp + nt4 * 8 + 2 * tg;
                float2 v;
                v.x = f2tf(acc[mt][nt4][2 * h]     * inv);
                v.y = f2tf(acc[mt][nt4][2 * h + 1] * inv);
                *(float2*)(dst + col) = v;
            }
        }
#undef STAGE
}

// ---------------------------------------------------------------------------
// Kernel 4: fused maxsim, COMPACTED doc columns (round-5 skeleton).
// Block = (doc c, quarter qq). Grid (256, 4). 512 threads (16 warps).
// B = compacted doc rows (nc ~ 128) gathered once via idx list; NT = ceil(nc/64)
// N-tiles (mostly 2) of 64 cols, 8 N-warps x 8 cols each.
// A tiles (4 queries, 124 rows pad 128) cp.async-staged; next-tile A prefetch
// overlaps the epilogue. Warps 2(M) x 8(N); per-warp M rows 64 (Mt=4).
// smem: A 128x132 + B 256x132 + red 8x128 + rowmax + idx = ~208 KB, 1 CTA/SM.
// ---------------------------------------------------------------------------
#define MS_SA 132
#define MS_SB 132
#define MSA_FLOATS (128 * MS_SA)
#define MSB_FLOATS (256 * MS_SB)
#define MS_SMEM_FLOATS (MSA_FLOATS + MSB_FLOATS + 8 * 128 + 128 + 256)
#define MS_SMEM_BYTES  (MS_SMEM_FLOATS * 4)

__global__ __launch_bounds__(512, 1) void maxsim_kernel(float* __restrict__ out) {
    extern __shared__ float sm[];
    float* As     = sm;                        // [m=128][k=128] stride 132
    float* Bs     = sm + MSA_FLOATS;           // [n<=256][k=128] stride 132
    float* red    = Bs + MSB_FLOATS;           // [8][128]
    float* rowmax = red + 8 * 128;             // [128]
    int*   sidx   = (int*)(rowmax + 128);      // [256]

    int t = threadIdx.x;
    int w = t >> 5, lane = t & 31, g = lane >> 2, tg = lane & 3;
    int mw = w & 1, nw = w >> 1;               // 2 M-warps, 8 N-warps
    int m_warp = mw * 64;

    int c  = blockIdx.x;                       // doc 0..255
    int qq = blockIdx.y;                       // quarter 0..3

    int nc = g_cnt[c];
    int NT = (nc + 63) >> 6;                   // 1..4 N-tiles of 64

    if (t < 256) sidx[t] = g_idx[c * 256 + t];
    // Zero A pad rows (124..127).
    if (t < 128) {
#pragma unroll
        for (int m = 124; m < 128; m++) As[m * MS_SA + t] = 0.f;
    }
    // Zero B pad rows [nc, NT*64).
    {
        int padrows = NT * 64 - nc;
        int tot4 = padrows * 32;
        for (int j = 0; j < 4; j++) {
            int idx = t + j * 512;
            if (idx < tot4) {
                int n = nc + (idx >> 5), k4 = idx & 31;
                *(float4*)&Bs[n * MS_SB + k4 * 4] = make_float4(0.f, 0.f, 0.f, 0.f);
            }
        }
    }
    __syncthreads();   // sidx visible before gather

    // Gather-stage B once: nc rows x 32 float4.
    {
        const float* base = g_col + (size_t)(QROWS + c * CT) * D;
        int chunks = nc * 32;
#pragma unroll
        for (int j = 0; j < 16; j++) {
            int idx = t + j * 512;
            if (idx < chunks) {
                int n = idx >> 5, k4 = idx & 31;
                CP_ASYNC16(smem_u32(&Bs[n * MS_SB + k4 * 4]),
                           base + (size_t)sidx[n] * D + k4 * 4);
            }
        }
    }
    CP_COMMIT();

    // Stage A tile: 124 rows x 32 float4 = 3968 chunks.
#define STAGEA(QT_) do {                                                         \
    const float* abase = g_col + (size_t)(QT_) * 124 * D;                        \
    _Pragma("unroll")                                                            \
    for (int j = 0; j < 8; j++) {                                                \
        int idx = t + j * 512;                                                   \
        if (idx < 3968) {                                                        \
            int m = idx >> 5, k4 = idx & 31;                                     \
            CP_ASYNC16(smem_u32(&As[m * MS_SA + k4 * 4]),                        \
                       abase + (size_t)m * D + k4 * 4);                          \
        }                                                                        \
    }                                                                            \
} while (0)

    STAGEA(qq * 4);
    CP_COMMIT();

    for (int i = 0; i < 4; i++) {
        int qt = qq * 4 + i;
        CP_WAIT0();
        __syncthreads();

        float acc[4][4][4];
#pragma unroll
        for (int mt = 0; mt < 4; mt++)
#pragma unroll
            for (int nt = 0; nt < 4; nt++)
#pragma unroll
                for (int k = 0; k < 4; k++) acc[mt][nt][k] = 0.f;

#pragma unroll 2
        for (int ks = 0; ks < 16; ks++) {
            int k0 = ks * 8;
            uint32_t afr[4][4], bfr[4][2];
#pragma unroll
            for (int mt = 0; mt < 4; mt++) {
                int base = m_warp + mt * 16;
                afr[mt][0] = __float_as_uint(As[(base + g)     * MS_SA + k0 + tg]);
                afr[mt][1] = __float_as_uint(As[(base + g + 8) * MS_SA + k0 + tg]);
                afr[mt][2] = __float_as_uint(As[(base + g)     * MS_SA + k0 + tg + 4]);
                afr[mt][3] = __float_as_uint(As[(base + g + 8) * MS_SA + k0 + tg + 4]);
            }
            for (int nt = 0; nt < NT; nt++) {
                int n = nt * 64 + nw * 8 + g;
                bfr[nt][0] = __float_as_uint(Bs[n * MS_SB + k0 + tg]);
                bfr[nt][1] = __float_as_uint(Bs[n * MS_SB + k0 + tg + 4]);
            }
            for (int nt = 0; nt < NT; nt++)
#pragma unroll
                for (int mt = 0; mt < 4; mt++)
                    mma_tf32(acc[mt][nt], afr[mt], bfr[nt]);
        }

        // Fused row-max over compacted cols (guard j < nc).
        float rp[4][2];
#pragma unroll
        for (int mt = 0; mt < 4; mt++) { rp[mt][0] = -INFINITY; rp[mt][1] = -INFINITY; }
        for (int nt = 0; nt < NT; nt++)
#pragma unroll
            for (int mt = 0; mt < 4; mt++)
#pragma unroll
                for (int k = 0; k < 4; k++) {
                    int j = nt * 64 + nw * 8 + 2 * tg + (k & 1);
                    if (j < nc) rp[mt][k >> 1] = fmaxf(rp[mt][k >> 1], acc[mt][nt][k]);
                }
#pragma unroll
        for (int off = 1; off <= 2; off <<= 1)
#pragma unroll
            for (int mt = 0; mt < 4; mt++)
#pragma unroll
                for (int h = 0; h < 2; h++)
                    rp[mt][h] = fmaxf(rp[mt][h], __shfl_xor_sync(0xffffffffu, rp[mt][h], off));
        if (tg == 0) {
#pragma unroll
            for (int mt = 0; mt < 4; mt++)
#pragma unroll
                for (int h = 0; h < 2; h++)
                    red[nw * 128 + m_warp + mt * 16 + g + 8 * h] = rp[mt][h];
        }
        __syncthreads();

        // Prefetch next A tile NOW — overlaps the remaining epilogue.
        if (i < 3) {
            STAGEA(qt + 1);
            CP_COMMIT();
        }

        if (t < 124) {
            float mx = red[t];
#pragma unroll
            for (int r8 = 1; r8 < 8; r8++) mx = fmaxf(mx, red[r8 * 128 + t]);
            rowmax[t] = mx;
        }
        __syncthreads();
        if (t < 4) {
            int q = qt * 4 + t;
            float s = 0.f;
#pragma unroll
            for (int k = 0; k < 31; k++) s += rowmax[t * 31 + k];
            out[q * CC + c] = s / g_denom[q];
        }
        // loop-top CP_WAIT0 + __syncthreads guards red/rowmax/As reuse
    }
#undef STAGEA
}

// ---------------------------------------------------------------------------
extern "C" void kernel_launch(void* const* d_in, const int* in_sizes, int n_in,
                              void* d_out, int out_size) {
    const float* qh  = (const float*)d_in[0];
    const float* ch  = (const float*)d_in[1];
    const float* Wm  = (const float*)d_in[2];
    const float* bia = (const float*)d_in[3];
    const int*   qm  = (const int*)d_in[4];
    const int*   cm  = (const int*)d_in[5];
    float* out = (float*)d_out;

    cudaFuncSetAttribute(maxsim_kernel,
                         cudaFuncAttributeMaxDynamicSharedMemorySize,
                         MS_SMEM_BYTES);

    pooled_kernel<<<Q + CC, 256>>>(qh, ch, qm, cm, out);
    denom_kernel<<<1, 64>>>(qm);
    compact_kernel<<<CC, 256>>>(cm);
    proj_kernel<<<NROWS / 64, 256>>>(qh, ch, Wm, bia, qm, cm);
    maxsim_kernel<<<dim3(256, 4), 512, MS_SMEM_BYTES>>>(out);
}

// round 8
// speedup vs baseline: 4.1185x; 4.1185x over previous
#include <cuda_runtime.h>
#include <math.h>
#include <stdint.h>

// Problem dims
#define Q    64
#define SQ   32
#define CC   256
#define SC   256
#define H    768
#define D    128
#define QT   31
#define CT   255
#define QROWS (Q*QT)     // 1984
#define CROWS (CC*CT)    // 65280
#define NROWS (QROWS+CROWS)

// Scratch
__device__ float g_col[(size_t)NROWS * D];
__device__ float g_denom[Q];
__device__ int   g_idx[CC * 256];   // per-doc compacted token indices (0-based in doc)
__device__ int   g_cnt[CC];         // per-doc compact count (unmasked + 1 masked rep)

// ---------------------------------------------------------------------------
// helpers
// ---------------------------------------------------------------------------
__device__ __forceinline__ float f2tf(float x) {
    uint32_t r;
    asm("cvt.rna.tf32.f32 %0, %1;" : "=r"(r) : "f"(x));
    return __uint_as_float(r);
}
__device__ __forceinline__ void mma_tf32(float* c, const uint32_t* a, const uint32_t* b) {
    asm volatile(
        "mma.sync.aligned.m16n8k8.row.col.f32.tf32.tf32.f32 "
        "{%0,%1,%2,%3},{%4,%5,%6,%7},{%8,%9},{%0,%1,%2,%3};\n"
        : "+f"(c[0]), "+f"(c[1]), "+f"(c[2]), "+f"(c[3])
        : "r"(a[0]), "r"(a[1]), "r"(a[2]), "r"(a[3]), "r"(b[0]), "r"(b[1]));
}
__device__ __forceinline__ uint32_t smem_u32(const void* p) {
    uint32_t a;
    asm("{ .reg .u64 t; cvta.to.shared.u64 t, %1; cvt.u32.u64 %0, t; }" : "=r"(a) : "l"(p));
    return a;
}
#define CP_ASYNC16(dst_u32, src_ptr) \
    asm volatile("cp.async.ca.shared.global [%0], [%1], 16;" :: "r"(dst_u32), "l"(src_ptr))
#define CP_COMMIT() asm volatile("cp.async.commit_group;" ::: "memory")
#define CP_WAIT1()  asm volatile("cp.async.wait_group 1;" ::: "memory")
#define CP_WAIT0()  asm volatile("cp.async.wait_group 0;" ::: "memory")

// ---------------------------------------------------------------------------
// Kernel 1: pooled vectors (fp32 exact)
// ---------------------------------------------------------------------------
__global__ void pooled_kernel(const float* __restrict__ qh,
                              const float* __restrict__ ch,
                              const int*   __restrict__ qm,
                              const int*   __restrict__ cm,
                              float* __restrict__ out) {
    int r = blockIdx.x;
    const float* src;
    float mask;
    float* dst;
    if (r < Q) {
        src  = qh + (size_t)r * SQ * H;
        mask = (float)qm[r * SQ];
        dst  = out + Q * CC + (size_t)r * H;
    } else {
        int c = r - Q;
        src  = ch + (size_t)c * SC * H;
        mask = (float)cm[c * SC];
        dst  = out + Q * CC + Q * H + (size_t)c * H;
    }
    __shared__ float red[8];
    int t = threadIdx.x;
    float v[3];
    float s = 0.f;
#pragma unroll
    for (int it = 0; it < 3; it++) {
        float x = src[t + it * 256] * mask;
        v[it] = x;
        s += x * x;
    }
#pragma unroll
    for (int o = 16; o; o >>= 1) s += __shfl_xor_sync(0xffffffffu, s, o);
    if ((t & 31) == 0) red[t >> 5] = s;
    __syncthreads();
    if (t < 8) {
        float ss = red[t];
#pragma unroll
        for (int o = 4; o; o >>= 1) ss += __shfl_xor_sync(0xffu, ss, o);
        if (t == 0) red[0] = ss;
    }
    __syncthreads();
    float inv = 1.f / fmaxf(sqrtf(red[0]), 1e-12f);
#pragma unroll
    for (int it = 0; it < 3; it++) dst[t + it * 256] = v[it] * inv;
}

// ---------------------------------------------------------------------------
// Kernel 2: denominators
// ---------------------------------------------------------------------------
__global__ void denom_kernel(const int* __restrict__ qm) {
    int q = threadIdx.x;
    if (q < Q) {
        int s = 0;
        for (int i = 1; i < SQ; i++) s += qm[q * SQ + i];
        g_denom[q] = (float)s;
    }
}

// ---------------------------------------------------------------------------
// Kernel 2b: per-doc token compaction (unmasked + 1 masked representative).
// ---------------------------------------------------------------------------
__global__ void compact_kernel(const int* __restrict__ cm) {
    int c = blockIdx.x, t = threadIdx.x;
    __shared__ int wcnt[8];
    __shared__ int firstmask;
    if (t == 0) firstmask = 1 << 30;
    __syncthreads();
    int valid = (t >= 1);
    int m = valid ? cm[c * SC + t] : 0;
    unsigned bal = __ballot_sync(0xffffffffu, m != 0);
    int w = t >> 5, lane = t & 31;
    int pre = __popc(bal & ((1u << lane) - 1));
    if (lane == 0) wcnt[w] = __popc(bal);
    if (valid && !m) atomicMin(&firstmask, t);
    __syncthreads();
    int off = 0;
    for (int i = 0; i < w; i++) off += wcnt[i];
    if (valid && m) g_idx[c * 256 + off + pre] = t - 1;
    if (t == 0) {
        int total = 0;
        for (int i = 0; i < 8; i++) total += wcnt[i];
        if (firstmask < 256) { g_idx[c * 256 + total] = firstmask - 1; total++; }
        g_cnt[c] = total;
    }
}

// ---------------------------------------------------------------------------
// Kernel 3: projection + l2norm (unchanged)
// ---------------------------------------------------------------------------
#define P_SA 36
#define P_SW 132
__global__ __launch_bounds__(256) void proj_kernel(const float* __restrict__ qh,
                                                   const float* __restrict__ ch,
                                                   const float* __restrict__ Wm,
                                                   const float* __restrict__ bias,
                                                   const int*   __restrict__ qm,
                                                   const int*   __restrict__ cm) {
    __shared__ float As[2][64 * P_SA];
    __shared__ float Ws[2][32 * P_SW];
    __shared__ float rowsq[64][4];
    __shared__ float invn[64];
    __shared__ const float* srcp[64];
    __shared__ float mk[64];

    int t = threadIdx.x;
    int w = t >> 5, lane = t & 31, g = lane >> 2, tg = lane & 3;
    int mw = w & 1, nw = w >> 1;
    int m_warp = mw * 32, n_warp = nw * 32;

    if (t < 64) {
        int r = blockIdx.x * 64 + t;
        if (r < QROWS) {
            int q = r / QT, i = r - q * QT;
            srcp[t] = qh + (size_t)(q * SQ + i + 1) * H;
            mk[t]   = (float)qm[q * SQ + i + 1];
        } else {
            int rc = r - QROWS;
            int c = rc / CT, j = rc - c * CT;
            srcp[t] = ch + (size_t)(c * SC + j + 1) * H;
            mk[t]   = (float)cm[c * SC + j + 1];
        }
    }

    float binit[4][2];
#pragma unroll
    for (int nt4 = 0; nt4 < 4; nt4++) {
        int col = n_warp + nt4 * 8 + 2 * tg;
        binit[nt4][0] = bias[col];
        binit[nt4][1] = bias[col + 1];
    }
    __syncthreads();

    uint32_t sA0 = smem_u32(&As[0][0]), sA1 = smem_u32(&As[1][0]);
    uint32_t sW0 = smem_u32(&Ws[0][0]), sW1 = smem_u32(&Ws[1][0]);

#define STAGE(bufA, bufW, KT) do {                                              \
    _Pragma("unroll")                                                           \
    for (int itc = 0; itc < 2; itc++) {                                         \
        int idx = t + itc * 256;                                                \
        int m = idx >> 3, k4 = idx & 7;                                         \
        CP_ASYNC16((bufA) + (m * P_SA + k4 * 4) * 4, srcp[m] + (KT) + k4 * 4);  \
    }                                                                           \
    _Pragma("unroll")                                                           \
    for (int itc = 0; itc < 4; itc++) {                                         \
        int idx = t + itc * 256;                                                \
        int k = idx >> 5, d4 = idx & 31;                                        \
        CP_ASYNC16((bufW) + (k * P_SW + d4 * 4) * 4,                            \
                   Wm + (size_t)((KT) + k) * D + d4 * 4);                       \
    }                                                                           \
} while (0)

    STAGE(sA0, sW0, 0);
    CP_COMMIT();

    float acc[2][4][4];
#pragma unroll
    for (int mt = 0; mt < 2; mt++)
#pragma unroll
        for (int nt4 = 0; nt4 < 4; nt4++)
#pragma unroll
            for (int i = 0; i < 4; i++) acc[mt][nt4][i] = 0.f;

    for (int it = 0; it < 24; it++) {
        if (it < 23) {
            if (it & 1) STAGE(sA0, sW0, (it + 1) * 32);
            else        STAGE(sA1, sW1, (it + 1) * 32);
            CP_COMMIT();
            CP_WAIT1();
        } else {
            CP_WAIT0();
        }
        __syncthreads();
        const float* A = As[it & 1];
        const float* W = Ws[it & 1];
#pragma unroll
        for (int ks = 0; ks < 4; ks++) {
            int k0 = ks * 8;
            uint32_t afr[2][4], bfr[4][2];
#pragma unroll
            for (int mt = 0; mt < 2; mt++) {
                int base = m_warp + mt * 16;
                afr[mt][0] = __float_as_uint(A[(base + g)     * P_SA + k0 + tg]);
                afr[mt][1] = __float_as_uint(A[(base + g + 8) * P_SA + k0 + tg]);
                afr[mt][2] = __float_as_uint(A[(base + g)     * P_SA + k0 + tg + 4]);
                afr[mt][3] = __float_as_uint(A[(base + g + 8) * P_SA + k0 + tg + 4]);
            }
#pragma unroll
            for (int nt4 = 0; nt4 < 4; nt4++) {
                int col = n_warp + nt4 * 8 + g;
                bfr[nt4][0] = __float_as_uint(W[(k0 + tg)     * P_SW + col]);
                bfr[nt4][1] = __float_as_uint(W[(k0 + tg + 4) * P_SW + col]);
            }
#pragma unroll
            for (int mt = 0; mt < 2; mt++)
#pragma unroll
                for (int nt4 = 0; nt4 < 4; nt4++)
                    mma_tf32(acc[mt][nt4], afr[mt], bfr[nt4]);
        }
        __syncthreads();
    }

    float mrow[2][2];
#pragma unroll
    for (int mt = 0; mt < 2; mt++) {
        mrow[mt][0] = mk[m_warp + mt * 16 + g];
        mrow[mt][1] = mk[m_warp + mt * 16 + g + 8];
    }
#pragma unroll
    for (int mt = 0; mt < 2; mt++)
#pragma unroll
        for (int nt4 = 0; nt4 < 4; nt4++)
#pragma unroll
            for (int i = 0; i < 4; i++)
                acc[mt][nt4][i] = mrow[mt][i >> 1] * acc[mt][nt4][i] + binit[nt4][i & 1];

    float pr[2][2];
#pragma unroll
    for (int mt = 0; mt < 2; mt++)
#pragma unroll
        for (int h = 0; h < 2; h++) {
            float s = 0.f;
#pragma unroll
            for (int nt4 = 0; nt4 < 4; nt4++) {
                float c0 = acc[mt][nt4][2 * h], c1 = acc[mt][nt4][2 * h + 1];
                s += c0 * c0 + c1 * c1;
            }
            pr[mt][h] = s;
        }
#pragma unroll
    for (int off = 1; off <= 2; off <<= 1) {
#pragma unroll
        for (int mt = 0; mt < 2; mt++)
#pragma unroll
            for (int h = 0; h < 2; h++)
                pr[mt][h] += __shfl_xor_sync(0xffffffffu, pr[mt][h], off);
    }
    if (tg == 0) {
#pragma unroll
        for (int mt = 0; mt < 2; mt++)
#pragma unroll
            for (int h = 0; h < 2; h++)
                rowsq[m_warp + mt * 16 + g + 8 * h][nw] = pr[mt][h];
    }
    __syncthreads();
    if (t < 64) {
        float s = rowsq[t][0] + rowsq[t][1] + rowsq[t][2] + rowsq[t][3];
        invn[t] = 1.f / fmaxf(sqrtf(s), 1e-12f);
    }
    __syncthreads();

    size_t gbase = (size_t)blockIdx.x * 64;
#pragma unroll
    for (int mt = 0; mt < 2; mt++)
#pragma unroll
        for (int h = 0; h < 2; h++) {
            int r = m_warp + mt * 16 + g + 8 * h;
            float inv = invn[r];
            float* dst = g_col + (gbase + r) * D;
#pragma unroll
            for (int nt4 = 0; nt4 < 4; nt4++) {
                int col = n_warp + nt4 * 8 + 2 * tg;
                float2 v;
                v.x = f2tf(acc[mt][nt4][2 * h]     * inv);
                v.y = f2tf(acc[mt][nt4][2 * h + 1] * inv);
                *(float2*)(dst + col) = v;
            }
        }
#undef STAGE
}

// ---------------------------------------------------------------------------
// Kernel 4: fused maxsim, compacted docs, NT specialized at COMPILE TIME.
// Block = (doc c, quarter qq). Grid (256, 4). 512 threads (16 warps = 2Mx8N).
// All register indexing static per NT instantiation (no spills).
// ---------------------------------------------------------------------------
#define MS_SA 132
#define MS_SB 132
#define MSA_FLOATS (128 * MS_SA)
#define MSB_FLOATS (256 * MS_SB)
#define MS_SMEM_FLOATS (MSA_FLOATS + MSB_FLOATS + 8 * 128 + 128 + 256)
#define MS_SMEM_BYTES  (MS_SMEM_FLOATS * 4)

#define MS_STAGEA(QT_) do {                                                      \
    const float* abase_ = g_col + (size_t)(QT_) * 124 * D;                       \
    _Pragma("unroll")                                                            \
    for (int j = 0; j < 8; j++) {                                                \
        int idx = t + j * 512;                                                   \
        if (idx < 3968) {                                                        \
            int m = idx >> 5, k4 = idx & 31;                                     \
            CP_ASYNC16(smem_u32(&As[m * MS_SA + k4 * 4]),                        \
                       abase_ + (size_t)m * D + k4 * 4);                         \
        }                                                                        \
    }                                                                            \
} while (0)

template <int NT>
__device__ __forceinline__ void ms_body(float* As, const float* Bs, float* red,
                                        float* rowmax, float* __restrict__ out,
                                        int t, int c, int qq, int nc) {
    int w = t >> 5, lane = t & 31, g = lane >> 2, tg = lane & 3;
    int mw = w & 1, nw = w >> 1;
    int m_warp = mw * 64;

    for (int i = 0; i < 4; i++) {
        int qt = qq * 4 + i;
        CP_WAIT0();
        __syncthreads();

        float acc[4][NT][4];
#pragma unroll
        for (int mt = 0; mt < 4; mt++)
#pragma unroll
            for (int nt = 0; nt < NT; nt++)
#pragma unroll
                for (int k = 0; k < 4; k++) acc[mt][nt][k] = 0.f;

#pragma unroll 2
        for (int ks = 0; ks < 16; ks++) {
            int k0 = ks * 8;
            uint32_t afr[4][4], bfr[NT][2];
#pragma unroll
            for (int mt = 0; mt < 4; mt++) {
                int base = m_warp + mt * 16;
                afr[mt][0] = __float_as_uint(As[(base + g)     * MS_SA + k0 + tg]);
                afr[mt][1] = __float_as_uint(As[(base + g + 8) * MS_SA + k0 + tg]);
                afr[mt][2] = __float_as_uint(As[(base + g)     * MS_SA + k0 + tg + 4]);
                afr[mt][3] = __float_as_uint(As[(base + g + 8) * MS_SA + k0 + tg + 4]);
            }
#pragma unroll
            for (int nt = 0; nt < NT; nt++) {
                int n = nt * 64 + nw * 8 + g;
                bfr[nt][0] = __float_as_uint(Bs[n * MS_SB + k0 + tg]);
                bfr[nt][1] = __float_as_uint(Bs[n * MS_SB + k0 + tg + 4]);
            }
#pragma unroll
            for (int mt = 0; mt < 4; mt++)
#pragma unroll
                for (int nt = 0; nt < NT; nt++)
                    mma_tf32(acc[mt][nt], afr[mt], bfr[nt]);
        }

        // Fused row-max over compacted cols (guard j < nc).
        float rp[4][2];
#pragma unroll
        for (int mt = 0; mt < 4; mt++) { rp[mt][0] = -INFINITY; rp[mt][1] = -INFINITY; }
#pragma unroll
        for (int nt = 0; nt < NT; nt++)
#pragma unroll
            for (int mt = 0; mt < 4; mt++)
#pragma unroll
                for (int k = 0; k < 4; k++) {
                    int j = nt * 64 + nw * 8 + 2 * tg + (k & 1);
                    if (j < nc) rp[mt][k >> 1] = fmaxf(rp[mt][k >> 1], acc[mt][nt][k]);
                }
#pragma unroll
        for (int off = 1; off <= 2; off <<= 1)
#pragma unroll
            for (int mt = 0; mt < 4; mt++)
#pragma unroll
                for (int h = 0; h < 2; h++)
                    rp[mt][h] = fmaxf(rp[mt][h], __shfl_xor_sync(0xffffffffu, rp[mt][h], off));
        if (tg == 0) {
#pragma unroll
            for (int mt = 0; mt < 4; mt++)
#pragma unroll
                for (int h = 0; h < 2; h++)
                    red[nw * 128 + m_warp + mt * 16 + g + 8 * h] = rp[mt][h];
        }
        __syncthreads();

        // Prefetch next A tile NOW — overlaps remaining epilogue.
        if (i < 3) {
            MS_STAGEA(qt + 1);
            CP_COMMIT();
        }

        if (t < 124) {
            float mx = red[t];
#pragma unroll
            for (int r8 = 1; r8 < 8; r8++) mx = fmaxf(mx, red[r8 * 128 + t]);
            rowmax[t] = mx;
        }
        __syncthreads();
        if (t < 4) {
            int q = qt * 4 + t;
            float s = 0.f;
#pragma unroll
            for (int k = 0; k < 31; k++) s += rowmax[t * 31 + k];
            out[q * CC + c] = s / g_denom[q];
        }
        // loop-top CP_WAIT0 + __syncthreads guards red/rowmax/As reuse
    }
}

__global__ __launch_bounds__(512, 1) void maxsim_kernel(float* __restrict__ out) {
    extern __shared__ float sm[];
    float* As     = sm;                        // [m=128][k=128] stride 132
    float* Bs     = sm + MSA_FLOATS;           // [n<=256][k=128] stride 132
    float* red    = Bs + MSB_FLOATS;           // [8][128]
    float* rowmax = red + 8 * 128;             // [128]
    int*   sidx   = (int*)(rowmax + 128);      // [256]

    int t = threadIdx.x;
    int c  = blockIdx.x;                       // doc 0..255
    int qq = blockIdx.y;                       // quarter 0..3

    int nc = g_cnt[c];
    int NT = (nc + 63) >> 6;                   // 1..4

    if (t < 256) sidx[t] = g_idx[c * 256 + t];
    if (t < 128) {
#pragma unroll
        for (int m = 124; m < 128; m++) As[m * MS_SA + t] = 0.f;
    }
    {   // Zero B pad rows [nc, NT*64).
        int padrows = NT * 64 - nc;
        int tot4 = padrows * 32;
        for (int j = 0; j < 4; j++) {
            int idx = t + j * 512;
            if (idx < tot4) {
                int n = nc + (idx >> 5), k4 = idx & 31;
                *(float4*)&Bs[n * MS_SB + k4 * 4] = make_float4(0.f, 0.f, 0.f, 0.f);
            }
        }
    }
    __syncthreads();   // sidx visible before gather

    // Gather-stage B once: nc rows x 32 float4.
    {
        const float* base = g_col + (size_t)(QROWS + c * CT) * D;
        int chunks = nc * 32;
#pragma unroll
        for (int j = 0; j < 16; j++) {
            int idx = t + j * 512;
            if (idx < chunks) {
                int n = idx >> 5, k4 = idx & 31;
                CP_ASYNC16(smem_u32(&Bs[n * MS_SB + k4 * 4]),
                           base + (size_t)sidx[n] * D + k4 * 4);
            }
        }
    }
    CP_COMMIT();

    MS_STAGEA(qq * 4);
    CP_COMMIT();

    // Compile-time specialized body (nc is block-uniform -> no divergence).
    if (NT == 2)      ms_body<2>(As, Bs, red, rowmax, out, t, c, qq, nc);
    else if (NT == 3) ms_body<3>(As, Bs, red, rowmax, out, t, c, qq, nc);
    else if (NT == 1) ms_body<1>(As, Bs, red, rowmax, out, t, c, qq, nc);
    else              ms_body<4>(As, Bs, red, rowmax, out, t, c, qq, nc);
}

// ---------------------------------------------------------------------------
extern "C" void kernel_launch(void* const* d_in, const int* in_sizes, int n_in,
                              void* d_out, int out_size) {
    const float* qh  = (const float*)d_in[0];
    const float* ch  = (const float*)d_in[1];
    const float* Wm  = (const float*)d_in[2];
    const float* bia = (const float*)d_in[3];
    const int*   qm  = (const int*)d_in[4];
    const int*   cm  = (const int*)d_in[5];
    float* out = (float*)d_out;

    cudaFuncSetAttribute(maxsim_kernel,
                         cudaFuncAttributeMaxDynamicSharedMemorySize,
                         MS_SMEM_BYTES);

    pooled_kernel<<<Q + CC, 256>>>(qh, ch, qm, cm, out);
    denom_kernel<<<1, 64>>>(qm);
    compact_kernel<<<CC, 256>>>(cm);
    proj_kernel<<<NROWS / 64, 256>>>(qh, ch, Wm, bia, qm, cm);
    maxsim_kernel<<<dim3(256, 4), 512, MS_SMEM_BYTES>>>(out);
}

// round 9
// speedup vs baseline: 5.6003x; 1.3598x over previous
#include <cuda_runtime.h>
#include <math.h>
#include <stdint.h>

// Problem dims
#define Q    64
#define SQ   32
#define CC   256
#define SC   256
#define H    768
#define D    128
#define QT   31
#define CT   255
#define QROWS (Q*QT)     // 1984
#define CROWS (CC*CT)    // 65280
#define NROWS (QROWS+CROWS)

// Scratch
__device__ float g_col[(size_t)NROWS * D];
__device__ float g_denom[Q];          // nu per query (float)
__device__ int   g_idx[CC * 256];     // per-doc compacted token indices
__device__ int   g_cnt[CC];           // per-doc compact count
__device__ float g_cvec[D];           // l2norm(bias), tf32-rounded
__device__ float g_cmax[CC];          // per-doc max_j dot(cvec, col_j)
__device__ int   g_qoff[Q + 1];       // prefix of unmasked q-token counts
__device__ int   g_gqidx[QROWS];      // global compacted q-token rows (sorted by q, i)
__device__ int   g_tile_qs[16], g_tile_qe[16], g_tile_rs[16];
__device__ int   g_ntiles;
__device__ int   g_nun;               // count of unmasked rows (all)
__device__ int   g_unrows[NROWS];     // compacted unmasked row ids (any order)

// ---------------------------------------------------------------------------
// helpers
// ---------------------------------------------------------------------------
__device__ __forceinline__ float f2tf(float x) {
    uint32_t r;
    asm("cvt.rna.tf32.f32 %0, %1;" : "=r"(r) : "f"(x));
    return __uint_as_float(r);
}
__device__ __forceinline__ void mma_tf32(float* c, const uint32_t* a, const uint32_t* b) {
    asm volatile(
        "mma.sync.aligned.m16n8k8.row.col.f32.tf32.tf32.f32 "
        "{%0,%1,%2,%3},{%4,%5,%6,%7},{%8,%9},{%0,%1,%2,%3};\n"
        : "+f"(c[0]), "+f"(c[1]), "+f"(c[2]), "+f"(c[3])
        : "r"(a[0]), "r"(a[1]), "r"(a[2]), "r"(a[3]), "r"(b[0]), "r"(b[1]));
}
__device__ __forceinline__ uint32_t smem_u32(const void* p) {
    uint32_t a;
    asm("{ .reg .u64 t; cvta.to.shared.u64 t, %1; cvt.u32.u64 %0, t; }" : "=r"(a) : "l"(p));
    return a;
}
#define CP_ASYNC16(dst_u32, src_ptr) \
    asm volatile("cp.async.ca.shared.global [%0], [%1], 16;" :: "r"(dst_u32), "l"(src_ptr))
#define CP_COMMIT() asm volatile("cp.async.commit_group;" ::: "memory")
#define CP_WAIT1()  asm volatile("cp.async.wait_group 1;" ::: "memory")
#define CP_WAIT0()  asm volatile("cp.async.wait_group 0;" ::: "memory")

// ---------------------------------------------------------------------------
// Kernel 1: pooled vectors (fp32 exact)
// ---------------------------------------------------------------------------
__global__ void pooled_kernel(const float* __restrict__ qh,
                              const float* __restrict__ ch,
                              const int*   __restrict__ qm,
                              const int*   __restrict__ cm,
                              float* __restrict__ out) {
    int r = blockIdx.x;
    const float* src;
    float mask;
    float* dst;
    if (r < Q) {
        src  = qh + (size_t)r * SQ * H;
        mask = (float)qm[r * SQ];
        dst  = out + Q * CC + (size_t)r * H;
    } else {
        int c = r - Q;
        src  = ch + (size_t)c * SC * H;
        mask = (float)cm[c * SC];
        dst  = out + Q * CC + Q * H + (size_t)c * H;
    }
    __shared__ float red[8];
    int t = threadIdx.x;
    float v[3];
    float s = 0.f;
#pragma unroll
    for (int it = 0; it < 3; it++) {
        float x = src[t + it * 256] * mask;
        v[it] = x;
        s += x * x;
    }
#pragma unroll
    for (int o = 16; o; o >>= 1) s += __shfl_xor_sync(0xffffffffu, s, o);
    if ((t & 31) == 0) red[t >> 5] = s;
    __syncthreads();
    if (t < 8) {
        float ss = red[t];
#pragma unroll
        for (int o = 4; o; o >>= 1) ss += __shfl_xor_sync(0xffu, ss, o);
        if (t == 0) red[0] = ss;
    }
    __syncthreads();
    float inv = 1.f / fmaxf(sqrtf(red[0]), 1e-12f);
#pragma unroll
    for (int it = 0; it < 3; it++) dst[t + it * 256] = v[it] * inv;
}

// ---------------------------------------------------------------------------
// Kernel 2: prep — denom, cvec, q-token global compaction + tile packing.
// One block, 256 threads.
// ---------------------------------------------------------------------------
__global__ void prep_kernel(const float* __restrict__ bias,
                            const int*   __restrict__ qm) {
    __shared__ int s_nu[64];
    __shared__ int s_qoff[65];
    __shared__ float s_red[4];
    int t = threadIdx.x;
    if (t < 64) {
        int nu = 0;
        for (int i = 1; i < SQ; i++) nu += (qm[t * SQ + i] != 0);
        s_nu[t] = nu;
        g_denom[t] = (float)nu;
    }
    __syncthreads();
    if (t == 0) {
        int acc = 0;
        for (int q = 0; q < 64; q++) { s_qoff[q] = acc; acc += s_nu[q]; }
        s_qoff[64] = acc;
        // query-aligned tile packing, <=128 rows per tile
        int ntiles = 0, cur = 0;
        while (cur < 64) {
            int qs = cur;
            while (cur < 64 && (s_qoff[cur + 1] - s_qoff[qs]) <= 128) cur++;
            g_tile_qs[ntiles] = qs;
            g_tile_qe[ntiles] = cur;
            g_tile_rs[ntiles] = s_qoff[qs];
            ntiles++;
        }
        g_ntiles = ntiles;
        g_nun = 0;
    }
    __syncthreads();
    if (t < 65) g_qoff[t] = s_qoff[t];
    if (t < 64) {
        int pos = s_qoff[t];
        for (int i = 1; i < SQ; i++)
            if (qm[t * SQ + i] != 0) g_gqidx[pos++] = t * QT + i - 1;
    }
    // cvec = l2norm(bias), tf32-rounded
    float v = (t < D) ? bias[t] : 0.f;
    float s = v * v;
#pragma unroll
    for (int o = 16; o; o >>= 1) s += __shfl_xor_sync(0xffffffffu, s, o);
    if ((t & 31) == 0 && t < D) s_red[t >> 5] = s;
    __syncthreads();
    if (t < D) {
        float tot = s_red[0] + s_red[1] + s_red[2] + s_red[3];
        float inv = 1.f / fmaxf(sqrtf(tot), 1e-12f);
        g_cvec[t] = f2tf(v * inv);
    }
}

// ---------------------------------------------------------------------------
// Kernel 2b: per-doc token compaction (unmasked + 1 masked representative)
// + write cvec into the representative's g_col row.
// ---------------------------------------------------------------------------
__global__ void compact_kernel(const int* __restrict__ cm) {
    int c = blockIdx.x, t = threadIdx.x;
    __shared__ int wcnt[8];
    __shared__ int firstmask;
    if (t == 0) firstmask = 1 << 30;
    __syncthreads();
    int valid = (t >= 1);
    int m = valid ? cm[c * SC + t] : 0;
    unsigned bal = __ballot_sync(0xffffffffu, m != 0);
    int w = t >> 5, lane = t & 31;
    int pre = __popc(bal & ((1u << lane) - 1));
    if (lane == 0) wcnt[w] = __popc(bal);
    if (valid && !m) atomicMin(&firstmask, t);
    __syncthreads();
    int off = 0;
    for (int i = 0; i < w; i++) off += wcnt[i];
    if (valid && m) g_idx[c * 256 + off + pre] = t - 1;
    if (t == 0) {
        int total = 0;
        for (int i = 0; i < 8; i++) total += wcnt[i];
        if (firstmask < 256) { g_idx[c * 256 + total] = firstmask - 1; total++; }
        g_cnt[c] = total;
    }
    __syncthreads();
    if (firstmask < 256 && t < D) {
        size_t row = (size_t)QROWS + (size_t)c * CT + (firstmask - 1);
        g_col[row * D + t] = g_cvec[t];
    }
}

// ---------------------------------------------------------------------------
// Kernel 2c: global unmasked-row list (order-free; ticketed).
// ---------------------------------------------------------------------------
__global__ void unlist_kernel(const int* __restrict__ qm,
                              const int* __restrict__ cm) {
    int r = blockIdx.x * 256 + threadIdx.x;
    int m = 0;
    if (r < NROWS) {
        if (r < QROWS) { int q = r / QT, i = r % QT; m = qm[q * SQ + i + 1]; }
        else { int rc = r - QROWS; int c = rc / CT, j = rc % CT; m = cm[c * SC + j + 1]; }
    }
    unsigned bal = __ballot_sync(0xffffffffu, m != 0);
    int lane = threadIdx.x & 31;
    int cnt = __popc(bal);
    int pre = __popc(bal & ((1u << lane) - 1));
    int base = 0;
    if (lane == 0 && cnt) base = atomicAdd(&g_nun, cnt);
    base = __shfl_sync(0xffffffffu, base, 0);
    if (m) g_unrows[base + pre] = r;
}

// ---------------------------------------------------------------------------
// Kernel 3: projection + l2norm over UNMASKED rows only (compacted).
// Grid = NROWS/64 upper bound; blocks past g_nun exit.
// ---------------------------------------------------------------------------
#define P_SA 36
#define P_SW 132
__global__ __launch_bounds__(256) void proj_kernel(const float* __restrict__ qh,
                                                   const float* __restrict__ ch,
                                                   const float* __restrict__ Wm,
                                                   const float* __restrict__ bias) {
    int nun = g_nun;
    if (blockIdx.x * 64 >= nun) return;

    __shared__ float As[2][64 * P_SA];
    __shared__ float Ws[2][32 * P_SW];
    __shared__ float rowsq[64][4];
    __shared__ float invn[64];
    __shared__ const float* srcp[64];
    __shared__ int rowid[64];

    int t = threadIdx.x;
    int w = t >> 5, lane = t & 31, g = lane >> 2, tg = lane & 3;
    int mw = w & 1, nw = w >> 1;
    int m_warp = mw * 32, n_warp = nw * 32;

    if (t < 64) {
        int idx = blockIdx.x * 64 + t;
        if (idx < nun) {
            int r = g_unrows[idx];
            rowid[t] = r;
            if (r < QROWS) {
                int q = r / QT, i = r % QT;
                srcp[t] = qh + (size_t)(q * SQ + i + 1) * H;
            } else {
                int rc = r - QROWS;
                int c = rc / CT, j = rc % CT;
                srcp[t] = ch + (size_t)(c * SC + j + 1) * H;
            }
        } else {
            rowid[t] = -1;
            srcp[t] = qh;
        }
    }

    float binit[4][2];
#pragma unroll
    for (int nt4 = 0; nt4 < 4; nt4++) {
        int col = n_warp + nt4 * 8 + 2 * tg;
        binit[nt4][0] = bias[col];
        binit[nt4][1] = bias[col + 1];
    }
    __syncthreads();

    uint32_t sA0 = smem_u32(&As[0][0]), sA1 = smem_u32(&As[1][0]);
    uint32_t sW0 = smem_u32(&Ws[0][0]), sW1 = smem_u32(&Ws[1][0]);

#define STAGE(bufA, bufW, KT) do {                                              \
    _Pragma("unroll")                                                           \
    for (int itc = 0; itc < 2; itc++) {                                         \
        int idx = t + itc * 256;                                                \
        int m = idx >> 3, k4 = idx & 7;                                         \
        CP_ASYNC16((bufA) + (m * P_SA + k4 * 4) * 4, srcp[m] + (KT) + k4 * 4);  \
    }                                                                           \
    _Pragma("unroll")                                                           \
    for (int itc = 0; itc < 4; itc++) {                                         \
        int idx = t + itc * 256;                                                \
        int k = idx >> 5, d4 = idx & 31;                                        \
        CP_ASYNC16((bufW) + (k * P_SW + d4 * 4) * 4,                            \
                   Wm + (size_t)((KT) + k) * D + d4 * 4);                       \
    }                                                                           \
} while (0)

    STAGE(sA0, sW0, 0);
    CP_COMMIT();

    float acc[2][4][4];
#pragma unroll
    for (int mt = 0; mt < 2; mt++)
#pragma unroll
        for (int nt4 = 0; nt4 < 4; nt4++)
#pragma unroll
            for (int i = 0; i < 4; i++) acc[mt][nt4][i] = 0.f;

    for (int it = 0; it < 24; it++) {
        if (it < 23) {
            if (it & 1) STAGE(sA0, sW0, (it + 1) * 32);
            else        STAGE(sA1, sW1, (it + 1) * 32);
            CP_COMMIT();
            CP_WAIT1();
        } else {
            CP_WAIT0();
        }
        __syncthreads();
        const float* A = As[it & 1];
        const float* W = Ws[it & 1];
#pragma unroll
        for (int ks = 0; ks < 4; ks++) {
            int k0 = ks * 8;
            uint32_t afr[2][4], bfr[4][2];
#pragma unroll
            for (int mt = 0; mt < 2; mt++) {
                int base = m_warp + mt * 16;
                afr[mt][0] = __float_as_uint(A[(base + g)     * P_SA + k0 + tg]);
                afr[mt][1] = __float_as_uint(A[(base + g + 8) * P_SA + k0 + tg]);
                afr[mt][2] = __float_as_uint(A[(base + g)     * P_SA + k0 + tg + 4]);
                afr[mt][3] = __float_as_uint(A[(base + g + 8) * P_SA + k0 + tg + 4]);
            }
#pragma unroll
            for (int nt4 = 0; nt4 < 4; nt4++) {
                int col = n_warp + nt4 * 8 + g;
                bfr[nt4][0] = __float_as_uint(W[(k0 + tg)     * P_SW + col]);
                bfr[nt4][1] = __float_as_uint(W[(k0 + tg + 4) * P_SW + col]);
            }
#pragma unroll
            for (int mt = 0; mt < 2; mt++)
#pragma unroll
                for (int nt4 = 0; nt4 < 4; nt4++)
                    mma_tf32(acc[mt][nt4], afr[mt], bfr[nt4]);
        }
        __syncthreads();
    }

    // bias (rows are all unmasked -> no mask multiply)
#pragma unroll
    for (int mt = 0; mt < 2; mt++)
#pragma unroll
        for (int nt4 = 0; nt4 < 4; nt4++)
#pragma unroll
            for (int i = 0; i < 4; i++)
                acc[mt][nt4][i] += binit[nt4][i & 1];

    float pr[2][2];
#pragma unroll
    for (int mt = 0; mt < 2; mt++)
#pragma unroll
        for (int h = 0; h < 2; h++) {
            float s = 0.f;
#pragma unroll
            for (int nt4 = 0; nt4 < 4; nt4++) {
                float c0 = acc[mt][nt4][2 * h], c1 = acc[mt][nt4][2 * h + 1];
                s += c0 * c0 + c1 * c1;
            }
            pr[mt][h] = s;
        }
#pragma unroll
    for (int off = 1; off <= 2; off <<= 1) {
#pragma unroll
        for (int mt = 0; mt < 2; mt++)
#pragma unroll
            for (int h = 0; h < 2; h++)
                pr[mt][h] += __shfl_xor_sync(0xffffffffu, pr[mt][h], off);
    }
    if (tg == 0) {
#pragma unroll
        for (int mt = 0; mt < 2; mt++)
#pragma unroll
            for (int h = 0; h < 2; h++)
                rowsq[m_warp + mt * 16 + g + 8 * h][nw] = pr[mt][h];
    }
    __syncthreads();
    if (t < 64) {
        float s = rowsq[t][0] + rowsq[t][1] + rowsq[t][2] + rowsq[t][3];
        invn[t] = 1.f / fmaxf(sqrtf(s), 1e-12f);
    }
    __syncthreads();

#pragma unroll
    for (int mt = 0; mt < 2; mt++)
#pragma unroll
        for (int h = 0; h < 2; h++) {
            int r = m_warp + mt * 16 + g + 8 * h;
            int grow = rowid[r];
            if (grow >= 0) {
                float inv = invn[r];
                float* dst = g_col + (size_t)grow * D;
#pragma unroll
                for (int nt4 = 0; nt4 < 4; nt4++) {
                    int col = n_warp + nt4 * 8 + 2 * tg;
                    float2 v;
                    v.x = f2tf(acc[mt][nt4][2 * h]     * inv);
                    v.y = f2tf(acc[mt][nt4][2 * h + 1] * inv);
                    *(float2*)(dst + col) = v;
                }
            }
        }
#undef STAGE
}

// ---------------------------------------------------------------------------
// Kernel 3b: cmax(c) = max over compacted doc cols of dot(cvec, col).
// ---------------------------------------------------------------------------
__global__ void cmax_kernel() {
    int c = blockIdx.x, t = threadIdx.x;   // 256 threads
    __shared__ float s_cv[D];
    __shared__ float s_red2[8];
    if (t < D) s_cv[t] = g_cvec[t];
    __syncthreads();
    int nc = g_cnt[c];
    float best = -INFINITY;
    for (int j = t; j < nc; j += 256) {
        size_t row = (size_t)QROWS + (size_t)c * CT + g_idx[c * 256 + j];
        const float* col = g_col + row * D;
        float s = 0.f;
#pragma unroll 4
        for (int k = 0; k < D; k++) s += s_cv[k] * col[k];
        best = fmaxf(best, s);
    }
#pragma unroll
    for (int o = 16; o; o >>= 1) best = fmaxf(best, __shfl_xor_sync(0xffffffffu, best, o));
    if ((t & 31) == 0) s_red2[t >> 5] = best;
    __syncthreads();
    if (t == 0) {
        float b = s_red2[0];
        for (int i = 1; i < 8; i++) b = fmaxf(b, s_red2[i]);
        g_cmax[c] = b;
    }
}

// ---------------------------------------------------------------------------
// Kernel 4: fused maxsim, BOTH sides compacted. Grid (256, 4), 512 threads.
// Block (c, yy): tiles tt = yy*4+i (query-aligned, <=128 unmasked q rows).
// out[q][c] = (n_masked(q)*cmax(c) + sum over unmasked rowmax) / denom(q).
// ---------------------------------------------------------------------------
#define MS_SA 132
#define MS_SB 132
#define MSA_FLOATS (128 * MS_SA)
#define MSB_FLOATS (256 * MS_SB)
#define MS_SMEM_FLOATS (MSA_FLOATS + MSB_FLOATS + 8 * 128 + 128 + 256)
#define MS_SMEM_BYTES  (MS_SMEM_FLOATS * 4)

#define MS_STAGEA(TT_) do {                                                      \
    int rs_ = g_tile_rs[TT_];                                                    \
    int rows_ = g_qoff[g_tile_qe[TT_]] - rs_;                                    \
    int chunks_ = rows_ * 32;                                                    \
    _Pragma("unroll")                                                            \
    for (int j = 0; j < 8; j++) {                                                \
        int idx = t + j * 512;                                                   \
        if (idx < chunks_) {                                                     \
            int m = idx >> 5, k4 = idx & 31;                                     \
            int grow = g_gqidx[rs_ + m];                                         \
            CP_ASYNC16(smem_u32(&As[m * MS_SA + k4 * 4]),                        \
                       g_col + (size_t)grow * D + k4 * 4);                       \
        }                                                                        \
    }                                                                            \
} while (0)

template <int NT>
__device__ __forceinline__ void ms_body(float* As, const float* Bs, float* red,
                                        float* rowmax, float* __restrict__ out,
                                        int t, int c, int yy, int nc, int ntiles) {
    int w = t >> 5, lane = t & 31, g = lane >> 2, tg = lane & 3;
    int mw = w & 1, nw = w >> 1;
    int m_warp = mw * 64;

    for (int i = 0; i < 4; i++) {
        int tt = yy * 4 + i;
        if (tt >= ntiles) break;
        CP_WAIT0();
        __syncthreads();

        float acc[4][NT][4];
#pragma unroll
        for (int mt = 0; mt < 4; mt++)
#pragma unroll
            for (int nt = 0; nt < NT; nt++)
#pragma unroll
                for (int k = 0; k < 4; k++) acc[mt][nt][k] = 0.f;

#pragma unroll 2
        for (int ks = 0; ks < 16; ks++) {
            int k0 = ks * 8;
            uint32_t afr[4][4], bfr[NT][2];
#pragma unroll
            for (int mt = 0; mt < 4; mt++) {
                int base = m_warp + mt * 16;
                afr[mt][0] = __float_as_uint(As[(base + g)     * MS_SA + k0 + tg]);
                afr[mt][1] = __float_as_uint(As[(base + g + 8) * MS_SA + k0 + tg]);
                afr[mt][2] = __float_as_uint(As[(base + g)     * MS_SA + k0 + tg + 4]);
                afr[mt][3] = __float_as_uint(As[(base + g + 8) * MS_SA + k0 + tg + 4]);
            }
#pragma unroll
            for (int nt = 0; nt < NT; nt++) {
                int n = nt * 64 + nw * 8 + g;
                bfr[nt][0] = __float_as_uint(Bs[n * MS_SB + k0 + tg]);
                bfr[nt][1] = __float_as_uint(Bs[n * MS_SB + k0 + tg + 4]);
            }
#pragma unroll
            for (int mt = 0; mt < 4; mt++)
#pragma unroll
                for (int nt = 0; nt < NT; nt++)
                    mma_tf32(acc[mt][nt], afr[mt], bfr[nt]);
        }

        // Row-max over compacted cols (guard j < nc; garbage rows unused later).
        float rp[4][2];
#pragma unroll
        for (int mt = 0; mt < 4; mt++) { rp[mt][0] = -INFINITY; rp[mt][1] = -INFINITY; }
#pragma unroll
        for (int nt = 0; nt < NT; nt++)
#pragma unroll
            for (int mt = 0; mt < 4; mt++)
#pragma unroll
                for (int k = 0; k < 4; k++) {
                    int j = nt * 64 + nw * 8 + 2 * tg + (k & 1);
                    if (j < nc) rp[mt][k >> 1] = fmaxf(rp[mt][k >> 1], acc[mt][nt][k]);
                }
#pragma unroll
        for (int off = 1; off <= 2; off <<= 1)
#pragma unroll
            for (int mt = 0; mt < 4; mt++)
#pragma unroll
                for (int h = 0; h < 2; h++)
                    rp[mt][h] = fmaxf(rp[mt][h], __shfl_xor_sync(0xffffffffu, rp[mt][h], off));
        if (tg == 0) {
#pragma unroll
            for (int mt = 0; mt < 4; mt++)
#pragma unroll
                for (int h = 0; h < 2; h++)
                    red[nw * 128 + m_warp + mt * 16 + g + 8 * h] = rp[mt][h];
        }
        __syncthreads();

        // Prefetch next A tile — overlaps remaining epilogue.
        if (i < 3 && tt + 1 < ntiles) {
            MS_STAGEA(tt + 1);
            CP_COMMIT();
        }

        if (t < 128) {
            float mx = red[t];
#pragma unroll
            for (int r8 = 1; r8 < 8; r8++) mx = fmaxf(mx, red[r8 * 128 + t]);
            rowmax[t] = mx;
        }
        __syncthreads();

        // Per-query segment sum + masked contribution; deterministic store.
        if (t < 64) {
            int qs = g_tile_qs[tt], qe = g_tile_qe[tt];
            int qi = qs + t;
            if (qi < qe) {
                int rs = g_tile_rs[tt];
                int r0 = g_qoff[qi] - rs;
                int r1 = g_qoff[qi + 1] - rs;
                float s = 0.f;
                for (int r = r0; r < r1; r++) s += rowmax[r];
                float nu = g_denom[qi];
                out[qi * CC + c] = ((31.f - nu) * g_cmax[c] + s) / nu;
            }
        }
        __syncthreads();   // red/rowmax reusable next tile
    }
}

__global__ __launch_bounds__(512, 1) void maxsim_kernel(float* __restrict__ out) {
    extern __shared__ float sm[];
    float* As     = sm;                        // [m<=128][k=128] stride 132
    float* Bs     = sm + MSA_FLOATS;           // [n<=256][k=128] stride 132
    float* red    = Bs + MSB_FLOATS;           // [8][128]
    float* rowmax = red + 8 * 128;             // [128]
    int*   sidx   = (int*)(rowmax + 128);      // [256]

    int t  = threadIdx.x;
    int c  = blockIdx.x;                       // doc 0..255
    int yy = blockIdx.y;                       // tile group 0..3

    int ntiles = g_ntiles;
    if (yy * 4 >= ntiles) return;

    int nc = g_cnt[c];
    int NT = (nc + 63) >> 6;                   // 1..4

    if (t < 256) sidx[t] = g_idx[c * 256 + t];
    __syncthreads();

    // Gather-stage B once: nc rows x 32 float4.
    {
        const float* base = g_col + (size_t)(QROWS + c * CT) * D;
        int chunks = nc * 32;
#pragma unroll
        for (int j = 0; j < 16; j++) {
            int idx = t + j * 512;
            if (idx < chunks) {
                int n = idx >> 5, k4 = idx & 31;
                CP_ASYNC16(smem_u32(&Bs[n * MS_SB + k4 * 4]),
                           base + (size_t)sidx[n] * D + k4 * 4);
            }
        }
    }
    CP_COMMIT();

    MS_STAGEA(yy * 4);
    CP_COMMIT();

    if (NT == 2)      ms_body<2>(As, Bs, red, rowmax, out, t, c, yy, nc, ntiles);
    else if (NT == 3) ms_body<3>(As, Bs, red, rowmax, out, t, c, yy, nc, ntiles);
    else if (NT == 1) ms_body<1>(As, Bs, red, rowmax, out, t, c, yy, nc, ntiles);
    else              ms_body<4>(As, Bs, red, rowmax, out, t, c, yy, nc, ntiles);
}

// ---------------------------------------------------------------------------
extern "C" void kernel_launch(void* const* d_in, const int* in_sizes, int n_in,
                              void* d_out, int out_size) {
    const float* qh  = (const float*)d_in[0];
    const float* ch  = (const float*)d_in[1];
    const float* Wm  = (const float*)d_in[2];
    const float* bia = (const float*)d_in[3];
    const int*   qm  = (const int*)d_in[4];
    const int*   cm  = (const int*)d_in[5];
    float* out = (float*)d_out;

    cudaFuncSetAttribute(maxsim_kernel,
                         cudaFuncAttributeMaxDynamicSharedMemorySize,
                         MS_SMEM_BYTES);

    pooled_kernel<<<Q + CC, 256>>>(qh, ch, qm, cm, out);
    prep_kernel<<<1, 256>>>(bia, qm);
    compact_kernel<<<CC, 256>>>(cm);
    unlist_kernel<<<(NROWS + 255) / 256, 256>>>(qm, cm);
    proj_kernel<<<NROWS / 64, 256>>>(qh, ch, Wm, bia);
    cmax_kernel<<<CC, 256>>>();
    maxsim_kernel<<<dim3(CC, 4), 512, MS_SMEM_BYTES>>>(out);
}

// round 10
// speedup vs baseline: 7.1348x; 1.2740x over previous
#include <cuda_runtime.h>
#include <cuda_fp16.h>
#include <math.h>
#include <stdint.h>

// Problem dims
#define Q    64
#define SQ   32
#define CC   256
#define SC   256
#define H    768
#define D    128
#define QT   31
#define CT   255
#define QROWS (Q*QT)     // 1984
#define CROWS (CC*CT)    // 65280
#define NROWS (QROWS+CROWS)

// Scratch
__device__ __half g_colh[(size_t)NROWS * D];   // fp16 projected+normalized embeddings
__device__ float  g_denom[Q];
__device__ int    g_idx[CC * 256];
__device__ int    g_cnt[CC];
__device__ __half g_cvech[D];                  // l2norm(bias), fp16
__device__ float  g_cmax[CC];
__device__ int    g_qoff[Q + 1];
__device__ int    g_gqidx[QROWS];
__device__ int    g_tile_qs[16], g_tile_qe[16], g_tile_rs[16];
__device__ int    g_ntiles;
__device__ int    g_nun;
__device__ int    g_unrows[NROWS];

// ---------------------------------------------------------------------------
// helpers
// ---------------------------------------------------------------------------
__device__ __forceinline__ void mma_tf32(float* c, const uint32_t* a, const uint32_t* b) {
    asm volatile(
        "mma.sync.aligned.m16n8k8.row.col.f32.tf32.tf32.f32 "
        "{%0,%1,%2,%3},{%4,%5,%6,%7},{%8,%9},{%0,%1,%2,%3};\n"
        : "+f"(c[0]), "+f"(c[1]), "+f"(c[2]), "+f"(c[3])
        : "r"(a[0]), "r"(a[1]), "r"(a[2]), "r"(a[3]), "r"(b[0]), "r"(b[1]));
}
__device__ __forceinline__ void mma_f16(float* c, const uint32_t* a, const uint32_t* b) {
    asm volatile(
        "mma.sync.aligned.m16n8k16.row.col.f32.f16.f16.f32 "
        "{%0,%1,%2,%3},{%4,%5,%6,%7},{%8,%9},{%0,%1,%2,%3};\n"
        : "+f"(c[0]), "+f"(c[1]), "+f"(c[2]), "+f"(c[3])
        : "r"(a[0]), "r"(a[1]), "r"(a[2]), "r"(a[3]), "r"(b[0]), "r"(b[1]));
}
__device__ __forceinline__ uint32_t smem_u32(const void* p) {
    uint32_t a;
    asm("{ .reg .u64 t; cvta.to.shared.u64 t, %1; cvt.u32.u64 %0, t; }" : "=r"(a) : "l"(p));
    return a;
}
#define CP_ASYNC16(dst_u32, src_ptr) \
    asm volatile("cp.async.ca.shared.global [%0], [%1], 16;" :: "r"(dst_u32), "l"(src_ptr))
#define CP_COMMIT() asm volatile("cp.async.commit_group;" ::: "memory")
#define CP_WAIT1()  asm volatile("cp.async.wait_group 1;" ::: "memory")
#define CP_WAIT0()  asm volatile("cp.async.wait_group 0;" ::: "memory")

// ---------------------------------------------------------------------------
// Kernel 1: pooled vectors (fp32 exact)
// ---------------------------------------------------------------------------
__global__ void pooled_kernel(const float* __restrict__ qh,
                              const float* __restrict__ ch,
                              const int*   __restrict__ qm,
                              const int*   __restrict__ cm,
                              float* __restrict__ out) {
    int r = blockIdx.x;
    const float* src;
    float mask;
    float* dst;
    if (r < Q) {
        src  = qh + (size_t)r * SQ * H;
        mask = (float)qm[r * SQ];
        dst  = out + Q * CC + (size_t)r * H;
    } else {
        int c = r - Q;
        src  = ch + (size_t)c * SC * H;
        mask = (float)cm[c * SC];
        dst  = out + Q * CC + Q * H + (size_t)c * H;
    }
    __shared__ float red[8];
    int t = threadIdx.x;
    float v[3];
    float s = 0.f;
#pragma unroll
    for (int it = 0; it < 3; it++) {
        float x = src[t + it * 256] * mask;
        v[it] = x;
        s += x * x;
    }
#pragma unroll
    for (int o = 16; o; o >>= 1) s += __shfl_xor_sync(0xffffffffu, s, o);
    if ((t & 31) == 0) red[t >> 5] = s;
    __syncthreads();
    if (t < 8) {
        float ss = red[t];
#pragma unroll
        for (int o = 4; o; o >>= 1) ss += __shfl_xor_sync(0xffu, ss, o);
        if (t == 0) red[0] = ss;
    }
    __syncthreads();
    float inv = 1.f / fmaxf(sqrtf(red[0]), 1e-12f);
#pragma unroll
    for (int it = 0; it < 3; it++) dst[t + it * 256] = v[it] * inv;
}

// ---------------------------------------------------------------------------
// Kernel 2: prep — denom, cvec (fp16), q-token compaction + tile packing.
// ---------------------------------------------------------------------------
__global__ void prep_kernel(const float* __restrict__ bias,
                            const int*   __restrict__ qm) {
    __shared__ int s_nu[64];
    __shared__ int s_qoff[65];
    __shared__ float s_red[4];
    int t = threadIdx.x;
    if (t < 64) {
        int nu = 0;
        for (int i = 1; i < SQ; i++) nu += (qm[t * SQ + i] != 0);
        s_nu[t] = nu;
        g_denom[t] = (float)nu;
    }
    __syncthreads();
    if (t == 0) {
        int acc = 0;
        for (int q = 0; q < 64; q++) { s_qoff[q] = acc; acc += s_nu[q]; }
        s_qoff[64] = acc;
        int ntiles = 0, cur = 0;
        while (cur < 64) {
            int qs = cur;
            while (cur < 64 && (s_qoff[cur + 1] - s_qoff[qs]) <= 128) cur++;
            g_tile_qs[ntiles] = qs;
            g_tile_qe[ntiles] = cur;
            g_tile_rs[ntiles] = s_qoff[qs];
            ntiles++;
        }
        g_ntiles = ntiles;
        g_nun = 0;
    }
    __syncthreads();
    if (t < 65) g_qoff[t] = s_qoff[t];
    if (t < 64) {
        int pos = s_qoff[t];
        for (int i = 1; i < SQ; i++)
            if (qm[t * SQ + i] != 0) g_gqidx[pos++] = t * QT + i - 1;
    }
    float v = (t < D) ? bias[t] : 0.f;
    float s = v * v;
#pragma unroll
    for (int o = 16; o; o >>= 1) s += __shfl_xor_sync(0xffffffffu, s, o);
    if ((t & 31) == 0 && t < D) s_red[t >> 5] = s;
    __syncthreads();
    if (t < D) {
        float tot = s_red[0] + s_red[1] + s_red[2] + s_red[3];
        float inv = 1.f / fmaxf(sqrtf(tot), 1e-12f);
        g_cvech[t] = __float2half_rn(v * inv);
    }
}

// ---------------------------------------------------------------------------
// Kernel 2b: per-doc compaction + write cvec into rep row (fp16).
// ---------------------------------------------------------------------------
__global__ void compact_kernel(const int* __restrict__ cm) {
    int c = blockIdx.x, t = threadIdx.x;
    __shared__ int wcnt[8];
    __shared__ int firstmask;
    if (t == 0) firstmask = 1 << 30;
    __syncthreads();
    int valid = (t >= 1);
    int m = valid ? cm[c * SC + t] : 0;
    unsigned bal = __ballot_sync(0xffffffffu, m != 0);
    int w = t >> 5, lane = t & 31;
    int pre = __popc(bal & ((1u << lane) - 1));
    if (lane == 0) wcnt[w] = __popc(bal);
    if (valid && !m) atomicMin(&firstmask, t);
    __syncthreads();
    int off = 0;
    for (int i = 0; i < w; i++) off += wcnt[i];
    if (valid && m) g_idx[c * 256 + off + pre] = t - 1;
    if (t == 0) {
        int total = 0;
        for (int i = 0; i < 8; i++) total += wcnt[i];
        if (firstmask < 256) { g_idx[c * 256 + total] = firstmask - 1; total++; }
        g_cnt[c] = total;
    }
    __syncthreads();
    if (firstmask < 256 && t < D) {
        size_t row = (size_t)QROWS + (size_t)c * CT + (firstmask - 1);
        g_colh[row * D + t] = g_cvech[t];
    }
}

// ---------------------------------------------------------------------------
// Kernel 2c: global unmasked-row list.
// ---------------------------------------------------------------------------
__global__ void unlist_kernel(const int* __restrict__ qm,
                              const int* __restrict__ cm) {
    int r = blockIdx.x * 256 + threadIdx.x;
    int m = 0;
    if (r < NROWS) {
        if (r < QROWS) { int q = r / QT, i = r % QT; m = qm[q * SQ + i + 1]; }
        else { int rc = r - QROWS; int c = rc / CT, j = rc % CT; m = cm[c * SC + j + 1]; }
    }
    unsigned bal = __ballot_sync(0xffffffffu, m != 0);
    int lane = threadIdx.x & 31;
    int cnt = __popc(bal);
    int pre = __popc(bal & ((1u << lane) - 1));
    int base = 0;
    if (lane == 0 && cnt) base = atomicAdd(&g_nun, cnt);
    base = __shfl_sync(0xffffffffu, base, 0);
    if (m) g_unrows[base + pre] = r;
}

// ---------------------------------------------------------------------------
// Kernel 3: projection + l2norm over unmasked rows (tf32; fp16 output).
// ---------------------------------------------------------------------------
#define P_SA 36
#define P_SW 132
__global__ __launch_bounds__(256) void proj_kernel(const float* __restrict__ qh,
                                                   const float* __restrict__ ch,
                                                   const float* __restrict__ Wm,
                                                   const float* __restrict__ bias) {
    int nun = g_nun;
    if (blockIdx.x * 64 >= nun) return;

    __shared__ float As[2][64 * P_SA];
    __shared__ float Ws[2][32 * P_SW];
    __shared__ float rowsq[64][4];
    __shared__ float invn[64];
    __shared__ const float* srcp[64];
    __shared__ int rowid[64];

    int t = threadIdx.x;
    int w = t >> 5, lane = t & 31, g = lane >> 2, tg = lane & 3;
    int mw = w & 1, nw = w >> 1;
    int m_warp = mw * 32, n_warp = nw * 32;

    if (t < 64) {
        int idx = blockIdx.x * 64 + t;
        if (idx < nun) {
            int r = g_unrows[idx];
            rowid[t] = r;
            if (r < QROWS) {
                int q = r / QT, i = r % QT;
                srcp[t] = qh + (size_t)(q * SQ + i + 1) * H;
            } else {
                int rc = r - QROWS;
                int c = rc / CT, j = rc % CT;
                srcp[t] = ch + (size_t)(c * SC + j + 1) * H;
            }
        } else {
            rowid[t] = -1;
            srcp[t] = qh;
        }
    }

    float binit[4][2];
#pragma unroll
    for (int nt4 = 0; nt4 < 4; nt4++) {
        int col = n_warp + nt4 * 8 + 2 * tg;
        binit[nt4][0] = bias[col];
        binit[nt4][1] = bias[col + 1];
    }
    __syncthreads();

    uint32_t sA0 = smem_u32(&As[0][0]), sA1 = smem_u32(&As[1][0]);
    uint32_t sW0 = smem_u32(&Ws[0][0]), sW1 = smem_u32(&Ws[1][0]);

#define STAGE(bufA, bufW, KT) do {                                              \
    _Pragma("unroll")                                                           \
    for (int itc = 0; itc < 2; itc++) {                                         \
        int idx = t + itc * 256;                                                \
        int m = idx >> 3, k4 = idx & 7;                                         \
        CP_ASYNC16((bufA) + (m * P_SA + k4 * 4) * 4, srcp[m] + (KT) + k4 * 4);  \
    }                                                                           \
    _Pragma("unroll")                                                           \
    for (int itc = 0; itc < 4; itc++) {                                         \
        int idx = t + itc * 256;                                                \
        int k = idx >> 5, d4 = idx & 31;                                        \
        CP_ASYNC16((bufW) + (k * P_SW + d4 * 4) * 4,                            \
                   Wm + (size_t)((KT) + k) * D + d4 * 4);                       \
    }                                                                           \
} while (0)

    STAGE(sA0, sW0, 0);
    CP_COMMIT();

    float acc[2][4][4];
#pragma unroll
    for (int mt = 0; mt < 2; mt++)
#pragma unroll
        for (int nt4 = 0; nt4 < 4; nt4++)
#pragma unroll
            for (int i = 0; i < 4; i++) acc[mt][nt4][i] = 0.f;

    for (int it = 0; it < 24; it++) {
        if (it < 23) {
            if (it & 1) STAGE(sA0, sW0, (it + 1) * 32);
            else        STAGE(sA1, sW1, (it + 1) * 32);
            CP_COMMIT();
            CP_WAIT1();
        } else {
            CP_WAIT0();
        }
        __syncthreads();
        const float* A = As[it & 1];
        const float* W = Ws[it & 1];
#pragma unroll
        for (int ks = 0; ks < 4; ks++) {
            int k0 = ks * 8;
            uint32_t afr[2][4], bfr[4][2];
#pragma unroll
            for (int mt = 0; mt < 2; mt++) {
                int base = m_warp + mt * 16;
                afr[mt][0] = __float_as_uint(A[(base + g)     * P_SA + k0 + tg]);
                afr[mt][1] = __float_as_uint(A[(base + g + 8) * P_SA + k0 + tg]);
                afr[mt][2] = __float_as_uint(A[(base + g)     * P_SA + k0 + tg + 4]);
                afr[mt][3] = __float_as_uint(A[(base + g + 8) * P_SA + k0 + tg + 4]);
            }
#pragma unroll
            for (int nt4 = 0; nt4 < 4; nt4++) {
                int col = n_warp + nt4 * 8 + g;
                bfr[nt4][0] = __float_as_uint(W[(k0 + tg)     * P_SW + col]);
                bfr[nt4][1] = __float_as_uint(W[(k0 + tg + 4) * P_SW + col]);
            }
#pragma unroll
            for (int mt = 0; mt < 2; mt++)
#pragma unroll
                for (int nt4 = 0; nt4 < 4; nt4++)
                    mma_tf32(acc[mt][nt4], afr[mt], bfr[nt4]);
        }
        __syncthreads();
    }

#pragma unroll
    for (int mt = 0; mt < 2; mt++)
#pragma unroll
        for (int nt4 = 0; nt4 < 4; nt4++)
#pragma unroll
            for (int i = 0; i < 4; i++)
                acc[mt][nt4][i] += binit[nt4][i & 1];

    float pr[2][2];
#pragma unroll
    for (int mt = 0; mt < 2; mt++)
#pragma unroll
        for (int h = 0; h < 2; h++) {
            float s = 0.f;
#pragma unroll
            for (int nt4 = 0; nt4 < 4; nt4++) {
                float c0 = acc[mt][nt4][2 * h], c1 = acc[mt][nt4][2 * h + 1];
                s += c0 * c0 + c1 * c1;
            }
            pr[mt][h] = s;
        }
#pragma unroll
    for (int off = 1; off <= 2; off <<= 1) {
#pragma unroll
        for (int mt = 0; mt < 2; mt++)
#pragma unroll
            for (int h = 0; h < 2; h++)
                pr[mt][h] += __shfl_xor_sync(0xffffffffu, pr[mt][h], off);
    }
    if (tg == 0) {
#pragma unroll
        for (int mt = 0; mt < 2; mt++)
#pragma unroll
            for (int h = 0; h < 2; h++)
                rowsq[m_warp + mt * 16 + g + 8 * h][nw] = pr[mt][h];
    }
    __syncthreads();
    if (t < 64) {
        float s = rowsq[t][0] + rowsq[t][1] + rowsq[t][2] + rowsq[t][3];
        invn[t] = 1.f / fmaxf(sqrtf(s), 1e-12f);
    }
    __syncthreads();

#pragma unroll
    for (int mt = 0; mt < 2; mt++)
#pragma unroll
        for (int h = 0; h < 2; h++) {
            int r = m_warp + mt * 16 + g + 8 * h;
            int grow = rowid[r];
            if (grow >= 0) {
                float inv = invn[r];
                __half* dst = g_colh + (size_t)grow * D;
#pragma unroll
                for (int nt4 = 0; nt4 < 4; nt4++) {
                    int col = n_warp + nt4 * 8 + 2 * tg;
                    *(__half2*)(dst + col) =
                        __floats2half2_rn(acc[mt][nt4][2 * h] * inv,
                                          acc[mt][nt4][2 * h + 1] * inv);
                }
            }
        }
#undef STAGE
}

// ---------------------------------------------------------------------------
// Kernel 3b: cmax(c) = max over compacted doc cols of dot(cvec, col)  (fp16 in).
// ---------------------------------------------------------------------------
__global__ void cmax_kernel() {
    int c = blockIdx.x, t = threadIdx.x;
    __shared__ float s_cv[D];
    __shared__ float s_red2[8];
    if (t < D) s_cv[t] = __half2float(g_cvech[t]);
    __syncthreads();
    int nc = g_cnt[c];
    float best = -INFINITY;
    for (int j = t; j < nc; j += 256) {
        size_t row = (size_t)QROWS + (size_t)c * CT + g_idx[c * 256 + j];
        const __half* col = g_colh + row * D;
        float s = 0.f;
#pragma unroll 4
        for (int k = 0; k < D; k++) s += s_cv[k] * __half2float(col[k]);
        best = fmaxf(best, s);
    }
#pragma unroll
    for (int o = 16; o; o >>= 1) best = fmaxf(best, __shfl_xor_sync(0xffffffffu, best, o));
    if ((t & 31) == 0) s_red2[t >> 5] = best;
    __syncthreads();
    if (t == 0) {
        float b = s_red2[0];
        for (int i = 1; i < 8; i++) b = fmaxf(b, s_red2[i]);
        g_cmax[c] = b;
    }
}

// ---------------------------------------------------------------------------
// Kernel 4: fused maxsim — fp16 m16n8k16, both sides compacted.
// Grid (256, 4), 512 threads (16 warps = 2Mx8N), warp tile 64x(NT*8).
// smem: A 128x136h + B 256x136h + red/rowmax/sidx = 110 KB.
// ---------------------------------------------------------------------------
#define MS_SAH 136
#define MS_SBH 136
#define MSA_HALFS (128 * MS_SAH)
#define MSB_HALFS (256 * MS_SBH)
#define MS_SMEM_BYTES ((MSA_HALFS + MSB_HALFS) * 2 + (8 * 128 + 128) * 4 + 256 * 4)

#define MS_STAGEA(TT_) do {                                                      \
    int rs_ = g_tile_rs[TT_];                                                    \
    int rows_ = g_qoff[g_tile_qe[TT_]] - rs_;                                    \
    int chunks_ = rows_ * 16;                                                    \
    _Pragma("unroll")                                                            \
    for (int j = 0; j < 4; j++) {                                                \
        int idx = t + j * 512;                                                   \
        if (idx < chunks_) {                                                     \
            int m = idx >> 4, k8 = idx & 15;                                     \
            int grow = g_gqidx[rs_ + m];                                         \
            CP_ASYNC16(smem_u32(&Ash[m * MS_SAH + k8 * 8]),                      \
                       g_colh + (size_t)grow * D + k8 * 8);                      \
        }                                                                        \
    }                                                                            \
} while (0)

template <int NT>
__device__ __forceinline__ void ms_body(__half* Ash, const __half* Bsh, float* red,
                                        float* rowmax, float* __restrict__ out,
                                        int t, int c, int yy, int nc, int ntiles) {
    int w = t >> 5, lane = t & 31, g = lane >> 2, tg = lane & 3;
    int mw = w & 1, nw = w >> 1;
    int m_warp = mw * 64;

    for (int i = 0; i < 4; i++) {
        int tt = yy * 4 + i;
        if (tt >= ntiles) break;
        CP_WAIT0();
        __syncthreads();

        float acc[4][NT][4];
#pragma unroll
        for (int mt = 0; mt < 4; mt++)
#pragma unroll
            for (int nt = 0; nt < NT; nt++)
#pragma unroll
                for (int k = 0; k < 4; k++) acc[mt][nt][k] = 0.f;

#pragma unroll
        for (int ks = 0; ks < 8; ks++) {
            int k0 = ks * 16;
            uint32_t afr[4][4], bfr[NT][2];
#pragma unroll
            for (int mt = 0; mt < 4; mt++) {
                int base = m_warp + mt * 16;
                afr[mt][0] = *(const uint32_t*)&Ash[(base + g)     * MS_SAH + k0 + 2 * tg];
                afr[mt][1] = *(const uint32_t*)&Ash[(base + g + 8) * MS_SAH + k0 + 2 * tg];
                afr[mt][2] = *(const uint32_t*)&Ash[(base + g)     * MS_SAH + k0 + 2 * tg + 8];
                afr[mt][3] = *(const uint32_t*)&Ash[(base + g + 8) * MS_SAH + k0 + 2 * tg + 8];
            }
#pragma unroll
            for (int nt = 0; nt < NT; nt++) {
                int n = nt * 64 + nw * 8 + g;
                bfr[nt][0] = *(const uint32_t*)&Bsh[n * MS_SBH + k0 + 2 * tg];
                bfr[nt][1] = *(const uint32_t*)&Bsh[n * MS_SBH + k0 + 2 * tg + 8];
            }
#pragma unroll
            for (int mt = 0; mt < 4; mt++)
#pragma unroll
                for (int nt = 0; nt < NT; nt++)
                    mma_f16(acc[mt][nt], afr[mt], bfr[nt]);
        }

        // Row-max over compacted cols (guard j < nc).
        float rp[4][2];
#pragma unroll
        for (int mt = 0; mt < 4; mt++) { rp[mt][0] = -INFINITY; rp[mt][1] = -INFINITY; }
#pragma unroll
        for (int nt = 0; nt < NT; nt++)
#pragma unroll
            for (int mt = 0; mt < 4; mt++)
#pragma unroll
                for (int k = 0; k < 4; k++) {
                    int j = nt * 64 + nw * 8 + 2 * tg + (k & 1);
                    if (j < nc) rp[mt][k >> 1] = fmaxf(rp[mt][k >> 1], acc[mt][nt][k]);
                }
#pragma unroll
        for (int off = 1; off <= 2; off <<= 1)
#pragma unroll
            for (int mt = 0; mt < 4; mt++)
#pragma unroll
                for (int h = 0; h < 2; h++)
                    rp[mt][h] = fmaxf(rp[mt][h], __shfl_xor_sync(0xffffffffu, rp[mt][h], off));
        if (tg == 0) {
#pragma unroll
            for (int mt = 0; mt < 4; mt++)
#pragma unroll
                for (int h = 0; h < 2; h++)
                    red[nw * 128 + m_warp + mt * 16 + g + 8 * h] = rp[mt][h];
        }
        __syncthreads();

        // Prefetch next A tile — overlaps remaining epilogue.
        if (i < 3 && tt + 1 < ntiles) {
            MS_STAGEA(tt + 1);
            CP_COMMIT();
        }

        if (t < 128) {
            float mx = red[t];
#pragma unroll
            for (int r8 = 1; r8 < 8; r8++) mx = fmaxf(mx, red[r8 * 128 + t]);
            rowmax[t] = mx;
        }
        __syncthreads();

        if (t < 64) {
            int qs = g_tile_qs[tt], qe = g_tile_qe[tt];
            int qi = qs + t;
            if (qi < qe) {
                int rs = g_tile_rs[tt];
                int r0 = g_qoff[qi] - rs;
                int r1 = g_qoff[qi + 1] - rs;
                float s = 0.f;
                for (int r = r0; r < r1; r++) s += rowmax[r];
                float nu = g_denom[qi];
                out[qi * CC + c] = ((31.f - nu) * g_cmax[c] + s) / nu;
            }
        }
        __syncthreads();
    }
}

__global__ __launch_bounds__(512, 1) void maxsim_kernel(float* __restrict__ out) {
    extern __shared__ char smc[];
    __half* Ash   = (__half*)smc;                      // [m<=128][k=128] stride 136
    __half* Bsh   = Ash + MSA_HALFS;                   // [n<=256][k=128] stride 136
    float* red    = (float*)(Bsh + MSB_HALFS);         // [8][128]
    float* rowmax = red + 8 * 128;                     // [128]
    int*   sidx   = (int*)(rowmax + 128);              // [256]

    int t  = threadIdx.x;
    int c  = blockIdx.x;
    int yy = blockIdx.y;

    int ntiles = g_ntiles;
    if (yy * 4 >= ntiles) return;

    int nc = g_cnt[c];
    int NT = (nc + 63) >> 6;

    if (t < 256) sidx[t] = g_idx[c * 256 + t];
    __syncthreads();

    // Gather-stage B once: nc rows x 16 16B-chunks (fp16 rows are 256 B).
    {
        const __half* base = g_colh + (size_t)(QROWS + c * CT) * D;
        int chunks = nc * 16;
#pragma unroll
        for (int j = 0; j < 8; j++) {
            int idx = t + j * 512;
            if (idx < chunks) {
                int n = idx >> 4, k8 = idx & 15;
                CP_ASYNC16(smem_u32(&Bsh[n * MS_SBH + k8 * 8]),
                           base + (size_t)sidx[n] * D + k8 * 8);
            }
        }
    }
    CP_COMMIT();

    MS_STAGEA(yy * 4);
    CP_COMMIT();

    if (NT == 2)      ms_body<2>(Ash, Bsh, red, rowmax, out, t, c, yy, nc, ntiles);
    else if (NT == 3) ms_body<3>(Ash, Bsh, red, rowmax, out, t, c, yy, nc, ntiles);
    else if (NT == 1) ms_body<1>(Ash, Bsh, red, rowmax, out, t, c, yy, nc, ntiles);
    else              ms_body<4>(Ash, Bsh, red, rowmax, out, t, c, yy, nc, ntiles);
}

// ---------------------------------------------------------------------------
extern "C" void kernel_launch(void* const* d_in, const int* in_sizes, int n_in,
                              void* d_out, int out_size) {
    const float* qh  = (const float*)d_in[0];
    const float* ch  = (const float*)d_in[1];
    const float* Wm  = (const float*)d_in[2];
    const float* bia = (const float*)d_in[3];
    const int*   qm  = (const int*)d_in[4];
    const int*   cm  = (const int*)d_in[5];
    float* out = (float*)d_out;

    cudaFuncSetAttribute(maxsim_kernel,
                         cudaFuncAttributeMaxDynamicSharedMemorySize,
                         MS_SMEM_BYTES);

    pooled_kernel<<<Q + CC, 256>>>(qh, ch, qm, cm, out);
    prep_kernel<<<1, 256>>>(bia, qm);
    compact_kernel<<<CC, 256>>>(cm);
    unlist_kernel<<<(NROWS + 255) / 256, 256>>>(qm, cm);
    proj_kernel<<<NROWS / 64, 256>>>(qh, ch, Wm, bia);
    cmax_kernel<<<CC, 256>>>();
    maxsim_kernel<<<dim3(CC, 4), 512, MS_SMEM_BYTES>>>(out);
}

// round 11
// speedup vs baseline: 8.0019x; 1.1215x over previous
#include <cuda_runtime.h>
#include <cuda_fp16.h>
#include <math.h>
#include <stdint.h>

// Problem dims
#define Q    64
#define SQ   32
#define CC   256
#define SC   256
#define H    768
#define D    128
#define QT   31
#define CT   255
#define QROWS (Q*QT)     // 1984
#define CROWS (CC*CT)    // 65280
#define NROWS (QROWS+CROWS)

// Scratch
__device__ __half g_colh[(size_t)NROWS * D];
__device__ float  g_denom[Q];
__device__ int    g_idx[CC * 256];
__device__ int    g_cnt[CC];
__device__ float  g_cmax[CC];
__device__ int    g_qoff[Q + 1];
__device__ int    g_gqidx[QROWS];
__device__ int    g_tile_qs[16], g_tile_qe[16], g_tile_rs[16];
__device__ int    g_ntiles;
__device__ int    g_nun;            // ticket counter; left at 0 by end of sequence
__device__ int    g_unrows[NROWS];

// ---------------------------------------------------------------------------
// helpers
// ---------------------------------------------------------------------------
__device__ __forceinline__ void mma_tf32(float* c, const uint32_t* a, const uint32_t* b) {
    asm volatile(
        "mma.sync.aligned.m16n8k8.row.col.f32.tf32.tf32.f32 "
        "{%0,%1,%2,%3},{%4,%5,%6,%7},{%8,%9},{%0,%1,%2,%3};\n"
        : "+f"(c[0]), "+f"(c[1]), "+f"(c[2]), "+f"(c[3])
        : "r"(a[0]), "r"(a[1]), "r"(a[2]), "r"(a[3]), "r"(b[0]), "r"(b[1]));
}
__device__ __forceinline__ void mma_f16(float* c, const uint32_t* a, const uint32_t* b) {
    asm volatile(
        "mma.sync.aligned.m16n8k16.row.col.f32.f16.f16.f32 "
        "{%0,%1,%2,%3},{%4,%5,%6,%7},{%8,%9},{%0,%1,%2,%3};\n"
        : "+f"(c[0]), "+f"(c[1]), "+f"(c[2]), "+f"(c[3])
        : "r"(a[0]), "r"(a[1]), "r"(a[2]), "r"(a[3]), "r"(b[0]), "r"(b[1]));
}
__device__ __forceinline__ uint32_t smem_u32(const void* p) {
    uint32_t a;
    asm("{ .reg .u64 t; cvta.to.shared.u64 t, %1; cvt.u32.u64 %0, t; }" : "=r"(a) : "l"(p));
    return a;
}
#define CP_ASYNC16(dst_u32, src_ptr) \
    asm volatile("cp.async.ca.shared.global [%0], [%1], 16;" :: "r"(dst_u32), "l"(src_ptr))
#define CP_COMMIT() asm volatile("cp.async.commit_group;" ::: "memory")
#define CP_WAIT1()  asm volatile("cp.async.wait_group 1;" ::: "memory")
#define CP_WAIT0()  asm volatile("cp.async.wait_group 0;" ::: "memory")

// ---------------------------------------------------------------------------
// Kernel 1: setup — pooled + unlist + compact + prep, role per blockIdx.
// Grid 320 x 256 threads.
//   all b   : pooled row b (64 q + 256 c)
//   b < 263 : unlist chunk b (rows b*256..)
//   b < 256 : doc compaction c=b + cvec into masked-rep row
//   b == 319: q-side prep (denom, qoff, gqidx, tile packing)
// g_nun must be 0 on entry (static init; maxsim resets at sequence end).
// ---------------------------------------------------------------------------
__global__ void setup_kernel(const float* __restrict__ qh,
                             const float* __restrict__ ch,
                             const float* __restrict__ bias,
                             const int*   __restrict__ qm,
                             const int*   __restrict__ cm,
                             float* __restrict__ out) {
    int b = blockIdx.x, t = threadIdx.x;
    int lane = t & 31, w = t >> 5;

    // ---- Role 1: pooled (fp32 exact) ----
    {
        __shared__ float red[8];
        const float* src;
        float mask;
        float* dst;
        if (b < Q) {
            src  = qh + (size_t)b * SQ * H;
            mask = (float)qm[b * SQ];
            dst  = out + Q * CC + (size_t)b * H;
        } else {
            int c = b - Q;
            src  = ch + (size_t)c * SC * H;
            mask = (float)cm[c * SC];
            dst  = out + Q * CC + Q * H + (size_t)c * H;
        }
        float v[3];
        float s = 0.f;
#pragma unroll
        for (int it = 0; it < 3; it++) {
            float x = src[t + it * 256] * mask;
            v[it] = x;
            s += x * x;
        }
#pragma unroll
        for (int o = 16; o; o >>= 1) s += __shfl_xor_sync(0xffffffffu, s, o);
        if (lane == 0) red[w] = s;
        __syncthreads();
        if (t < 8) {
            float ss = red[t];
#pragma unroll
            for (int o = 4; o; o >>= 1) ss += __shfl_xor_sync(0xffu, ss, o);
            if (t == 0) red[0] = ss;
        }
        __syncthreads();
        float inv = 1.f / fmaxf(sqrtf(red[0]), 1e-12f);
#pragma unroll
        for (int it = 0; it < 3; it++) dst[t + it * 256] = v[it] * inv;
        __syncthreads();
    }

    // ---- Role 2: unlist (ticketed compaction of unmasked rows) ----
    if (b < 263) {
        int r = b * 256 + t;
        int m = 0;
        if (r < NROWS) {
            if (r < QROWS) { int q = r / QT, i = r % QT; m = qm[q * SQ + i + 1]; }
            else { int rc = r - QROWS; int c = rc / CT, j = rc % CT; m = cm[c * SC + j + 1]; }
        }
        unsigned bal = __ballot_sync(0xffffffffu, m != 0);
        int cnt = __popc(bal);
        int pre = __popc(bal & ((1u << lane) - 1));
        int base = 0;
        if (lane == 0 && cnt) base = atomicAdd(&g_nun, cnt);
        base = __shfl_sync(0xffffffffu, base, 0);
        if (m) g_unrows[base + pre] = r;
    }

    // ---- Role 3: doc compaction + cvec rep-row write ----
    if (b < 256) {
        __shared__ int wcnt[8];
        __shared__ int firstmask;
        __shared__ float s_cr[4];
        int c = b;
        if (t == 0) firstmask = 1 << 30;
        __syncthreads();
        int valid = (t >= 1);
        int m = valid ? cm[c * SC + t] : 0;
        unsigned bal = __ballot_sync(0xffffffffu, m != 0);
        int pre = __popc(bal & ((1u << lane) - 1));
        if (lane == 0) wcnt[w] = __popc(bal);
        if (valid && !m) atomicMin(&firstmask, t);
        __syncthreads();
        int off = 0;
        for (int i = 0; i < w; i++) off += wcnt[i];
        if (valid && m) g_idx[c * 256 + off + pre] = t - 1;
        if (t == 0) {
            int total = 0;
            for (int i = 0; i < 8; i++) total += wcnt[i];
            if (firstmask < 256) { g_idx[c * 256 + total] = firstmask - 1; total++; }
            g_cnt[c] = total;
        }
        // local cvec = l2norm(bias) -> rep row (fp16)
        float v = (t < D) ? bias[t] : 0.f;
        float sq = v * v;
#pragma unroll
        for (int o = 16; o; o >>= 1) sq += __shfl_xor_sync(0xffffffffu, sq, o);
        if (lane == 0 && t < D) s_cr[w] = sq;
        __syncthreads();
        if (firstmask < 256 && t < D) {
            float tot = s_cr[0] + s_cr[1] + s_cr[2] + s_cr[3];
            float inv = 1.f / fmaxf(sqrtf(tot), 1e-12f);
            size_t row = (size_t)QROWS + (size_t)c * CT + (firstmask - 1);
            g_colh[row * D + t] = __float2half_rn(v * inv);
        }
    }

    // ---- Role 4: q-side prep ----
    if (b == 319) {
        __shared__ int s_nu[64];
        __shared__ int s_qoff[65];
        if (t < 64) {
            int nu = 0;
            for (int i = 1; i < SQ; i++) nu += (qm[t * SQ + i] != 0);
            s_nu[t] = nu;
            g_denom[t] = (float)nu;
        }
        __syncthreads();
        if (t == 0) {
            int acc = 0;
            for (int q = 0; q < 64; q++) { s_qoff[q] = acc; acc += s_nu[q]; }
            s_qoff[64] = acc;
            int ntiles = 0, cur = 0;
            while (cur < 64) {
                int qs = cur;
                while (cur < 64 && (s_qoff[cur + 1] - s_qoff[qs]) <= 128) cur++;
                g_tile_qs[ntiles] = qs;
                g_tile_qe[ntiles] = cur;
                g_tile_rs[ntiles] = s_qoff[qs];
                ntiles++;
            }
            g_ntiles = ntiles;
        }
        __syncthreads();
        if (t < 65) g_qoff[t] = s_qoff[t];
        if (t < 64) {
            int pos = s_qoff[t];
            for (int i = 1; i < SQ; i++)
                if (qm[t * SQ + i] != 0) g_gqidx[pos++] = t * QT + i - 1;
        }
    }
}

// ---------------------------------------------------------------------------
// Kernel 2: projection + l2norm over unmasked rows. 128 rows/block.
// 8 warps = 4(M) x 2(N); warp tile 32x64 (Mt=2, Nt=8). tf32, fp16 out.
// Dynamic smem ~74 KB -> 2 CTA/SM; ~263 active blocks = one wave.
// ---------------------------------------------------------------------------
#define P_SA 36
#define P_SW 132
#define P_AS_F (128 * P_SA)            // 4608
#define P_WS_F (32 * P_SW)             // 4224
#define P_SMEM_FLOATS (2*P_AS_F + 2*P_WS_F + 256 /*srcp*/ + 128 /*rowid*/ + 256 /*rowsq*/ + 128 /*invn*/ + 128 /*bias*/)
#define P_SMEM_BYTES (P_SMEM_FLOATS * 4)

__global__ __launch_bounds__(256) void proj_kernel(const float* __restrict__ qh,
                                                   const float* __restrict__ ch,
                                                   const float* __restrict__ Wm,
                                                   const float* __restrict__ bias) {
    int nun = g_nun;
    if (blockIdx.x * 128 >= nun) return;

    extern __shared__ float psm[];
    float* As0 = psm;
    float* As1 = psm + P_AS_F;
    float* Ws0 = psm + 2 * P_AS_F;
    float* Ws1 = Ws0 + P_WS_F;
    const float** srcp = (const float**)(psm + 2 * P_AS_F + 2 * P_WS_F);
    int*   rowid  = (int*)(srcp + 128);
    float* rowsq  = (float*)(rowid + 128);      // [128][2]
    float* invn   = rowsq + 256;
    float* s_bias = invn + 128;

    int t = threadIdx.x;
    int w = t >> 5, lane = t & 31, g = lane >> 2, tg = lane & 3;
    int mw = w & 3, nw = w >> 2;
    int m_warp = mw * 32, n_warp = nw * 64;

    if (t < 128) {
        s_bias[t] = bias[t];
        int idx = blockIdx.x * 128 + t;
        if (idx < nun) {
            int r = g_unrows[idx];
            rowid[t] = r;
            if (r < QROWS) {
                int q = r / QT, i = r % QT;
                srcp[t] = qh + (size_t)(q * SQ + i + 1) * H;
            } else {
                int rc = r - QROWS;
                int c = rc / CT, j = rc % CT;
                srcp[t] = ch + (size_t)(c * SC + j + 1) * H;
            }
        } else {
            rowid[t] = -1;
            srcp[t] = qh;
        }
    }
    __syncthreads();

#define PSTAGE(bufA, bufW, KT) do {                                             \
    _Pragma("unroll")                                                           \
    for (int itc = 0; itc < 4; itc++) {                                         \
        int idx = t + itc * 256;                                                \
        int m = idx >> 3, k4 = idx & 7;                                         \
        CP_ASYNC16(smem_u32((bufA) + m * P_SA + k4 * 4), srcp[m] + (KT) + k4 * 4); \
    }                                                                           \
    _Pragma("unroll")                                                           \
    for (int itc = 0; itc < 4; itc++) {                                         \
        int idx = t + itc * 256;                                                \
        int k = idx >> 5, d4 = idx & 31;                                        \
        CP_ASYNC16(smem_u32((bufW) + k * P_SW + d4 * 4),                        \
                   Wm + (size_t)((KT) + k) * D + d4 * 4);                       \
    }                                                                           \
} while (0)

    PSTAGE(As0, Ws0, 0);
    CP_COMMIT();

    float acc[2][8][4];
#pragma unroll
    for (int mt = 0; mt < 2; mt++)
#pragma unroll
        for (int nt4 = 0; nt4 < 8; nt4++)
#pragma unroll
            for (int i = 0; i < 4; i++) acc[mt][nt4][i] = 0.f;

    for (int it = 0; it < 24; it++) {
        if (it < 23) {
            if (it & 1) PSTAGE(As0, Ws0, (it + 1) * 32);
            else        PSTAGE(As1, Ws1, (it + 1) * 32);
            CP_COMMIT();
            CP_WAIT1();
        } else {
            CP_WAIT0();
        }
        __syncthreads();
        const float* A = (it & 1) ? As1 : As0;
        const float* W = (it & 1) ? Ws1 : Ws0;
#pragma unroll
        for (int ks = 0; ks < 4; ks++) {
            int k0 = ks * 8;
            uint32_t afr[2][4], bfr[8][2];
#pragma unroll
            for (int mt = 0; mt < 2; mt++) {
                int base = m_warp + mt * 16;
                afr[mt][0] = __float_as_uint(A[(base + g)     * P_SA + k0 + tg]);
                afr[mt][1] = __float_as_uint(A[(base + g + 8) * P_SA + k0 + tg]);
                afr[mt][2] = __float_as_uint(A[(base + g)     * P_SA + k0 + tg + 4]);
                afr[mt][3] = __float_as_uint(A[(base + g + 8) * P_SA + k0 + tg + 4]);
            }
#pragma unroll
            for (int nt4 = 0; nt4 < 8; nt4++) {
                int col = n_warp + nt4 * 8 + g;
                bfr[nt4][0] = __float_as_uint(W[(k0 + tg)     * P_SW + col]);
                bfr[nt4][1] = __float_as_uint(W[(k0 + tg + 4) * P_SW + col]);
            }
#pragma unroll
            for (int mt = 0; mt < 2; mt++)
#pragma unroll
                for (int nt4 = 0; nt4 < 8; nt4++)
                    mma_tf32(acc[mt][nt4], afr[mt], bfr[nt4]);
        }
        __syncthreads();
    }

    // bias add (rows are unmasked -> no mask multiply)
#pragma unroll
    for (int mt = 0; mt < 2; mt++)
#pragma unroll
        for (int nt4 = 0; nt4 < 8; nt4++)
#pragma unroll
            for (int i = 0; i < 4; i++)
                acc[mt][nt4][i] += s_bias[n_warp + nt4 * 8 + 2 * tg + (i & 1)];

    // row-wise sum of squares -> invnorm
    float pr[2][2];
#pragma unroll
    for (int mt = 0; mt < 2; mt++)
#pragma unroll
        for (int h = 0; h < 2; h++) {
            float s = 0.f;
#pragma unroll
            for (int nt4 = 0; nt4 < 8; nt4++) {
                float c0 = acc[mt][nt4][2 * h], c1 = acc[mt][nt4][2 * h + 1];
                s += c0 * c0 + c1 * c1;
            }
            pr[mt][h] = s;
        }
#pragma unroll
    for (int off = 1; off <= 2; off <<= 1) {
#pragma unroll
        for (int mt = 0; mt < 2; mt++)
#pragma unroll
            for (int h = 0; h < 2; h++)
                pr[mt][h] += __shfl_xor_sync(0xffffffffu, pr[mt][h], off);
    }
    if (tg == 0) {
#pragma unroll
        for (int mt = 0; mt < 2; mt++)
#pragma unroll
            for (int h = 0; h < 2; h++)
                rowsq[(m_warp + mt * 16 + g + 8 * h) * 2 + nw] = pr[mt][h];
    }
    __syncthreads();
    if (t < 128) {
        float s = rowsq[t * 2] + rowsq[t * 2 + 1];
        invn[t] = 1.f / fmaxf(sqrtf(s), 1e-12f);
    }
    __syncthreads();

#pragma unroll
    for (int mt = 0; mt < 2; mt++)
#pragma unroll
        for (int h = 0; h < 2; h++) {
            int r = m_warp + mt * 16 + g + 8 * h;
            int grow = rowid[r];
            if (grow >= 0) {
                float inv = invn[r];
                __half* dst = g_colh + (size_t)grow * D;
#pragma unroll
                for (int nt4 = 0; nt4 < 8; nt4++) {
                    int col = n_warp + nt4 * 8 + 2 * tg;
                    *(__half2*)(dst + col) =
                        __floats2half2_rn(acc[mt][nt4][2 * h] * inv,
                                          acc[mt][nt4][2 * h + 1] * inv);
                }
            }
        }
#undef PSTAGE
}

// ---------------------------------------------------------------------------
// Kernel 3: cmax(c) = max over compacted doc cols of dot(cvec, col).
// cvec computed locally from bias.
// ---------------------------------------------------------------------------
__global__ void cmax_kernel(const float* __restrict__ bias) {
    int c = blockIdx.x, t = threadIdx.x;
    __shared__ float s_cv[D];
    __shared__ float s_cr[4];
    __shared__ float s_red2[8];
    float v = (t < D) ? bias[t] : 0.f;
    float sq = v * v;
#pragma unroll
    for (int o = 16; o; o >>= 1) sq += __shfl_xor_sync(0xffffffffu, sq, o);
    if ((t & 31) == 0 && t < D) s_cr[t >> 5] = sq;
    __syncthreads();
    if (t < D) {
        float tot = s_cr[0] + s_cr[1] + s_cr[2] + s_cr[3];
        s_cv[t] = v / fmaxf(sqrtf(tot), 1e-12f);
    }
    __syncthreads();
    int nc = g_cnt[c];
    float best = -INFINITY;
    for (int j = t; j < nc; j += 256) {
        size_t row = (size_t)QROWS + (size_t)c * CT + g_idx[c * 256 + j];
        const __half* col = g_colh + row * D;
        float s = 0.f;
#pragma unroll 4
        for (int k = 0; k < D; k++) s += s_cv[k] * __half2float(col[k]);
        best = fmaxf(best, s);
    }
#pragma unroll
    for (int o = 16; o; o >>= 1) best = fmaxf(best, __shfl_xor_sync(0xffffffffu, best, o));
    if ((t & 31) == 0) s_red2[t >> 5] = best;
    __syncthreads();
    if (t == 0) {
        float bmax = s_red2[0];
        for (int i = 1; i < 8; i++) bmax = fmaxf(bmax, s_red2[i]);
        g_cmax[c] = bmax;
    }
}

// ---------------------------------------------------------------------------
// Kernel 4: fused maxsim — fp16 m16n8k16, both sides compacted (unchanged).
// Also resets g_nun for the next kernel_launch invocation.
// ---------------------------------------------------------------------------
#define MS_SAH 136
#define MS_SBH 136
#define MSA_HALFS (128 * MS_SAH)
#define MSB_HALFS (256 * MS_SBH)
#define MS_SMEM_BYTES ((MSA_HALFS + MSB_HALFS) * 2 + (8 * 128 + 128) * 4 + 256 * 4)

#define MS_STAGEA(TT_) do {                                                      \
    int rs_ = g_tile_rs[TT_];                                                    \
    int rows_ = g_qoff[g_tile_qe[TT_]] - rs_;                                    \
    int chunks_ = rows_ * 16;                                                    \
    _Pragma("unroll")                                                            \
    for (int j = 0; j < 4; j++) {                                                \
        int idx = t + j * 512;                                                   \
        if (idx < chunks_) {                                                     \
            int m = idx >> 4, k8 = idx & 15;                                     \
            int grow = g_gqidx[rs_ + m];                                         \
            CP_ASYNC16(smem_u32(&Ash[m * MS_SAH + k8 * 8]),                      \
                       g_colh + (size_t)grow * D + k8 * 8);                      \
        }                                                                        \
    }                                                                            \
} while (0)

template <int NT>
__device__ __forceinline__ void ms_body(__half* Ash, const __half* Bsh, float* red,
                                        float* rowmax, float* __restrict__ out,
                                        int t, int c, int yy, int nc, int ntiles) {
    int w = t >> 5, lane = t & 31, g = lane >> 2, tg = lane & 3;
    int mw = w & 1, nw = w >> 1;
    int m_warp = mw * 64;

    for (int i = 0; i < 4; i++) {
        int tt = yy * 4 + i;
        if (tt >= ntiles) break;
        CP_WAIT0();
        __syncthreads();

        float acc[4][NT][4];
#pragma unroll
        for (int mt = 0; mt < 4; mt++)
#pragma unroll
            for (int nt = 0; nt < NT; nt++)
#pragma unroll
                for (int k = 0; k < 4; k++) acc[mt][nt][k] = 0.f;

#pragma unroll
        for (int ks = 0; ks < 8; ks++) {
            int k0 = ks * 16;
            uint32_t afr[4][4], bfr[NT][2];
#pragma unroll
            for (int mt = 0; mt < 4; mt++) {
                int base = m_warp + mt * 16;
                afr[mt][0] = *(const uint32_t*)&Ash[(base + g)     * MS_SAH + k0 + 2 * tg];
                afr[mt][1] = *(const uint32_t*)&Ash[(base + g + 8) * MS_SAH + k0 + 2 * tg];
                afr[mt][2] = *(const uint32_t*)&Ash[(base + g)     * MS_SAH + k0 + 2 * tg + 8];
                afr[mt][3] = *(const uint32_t*)&Ash[(base + g + 8) * MS_SAH + k0 + 2 * tg + 8];
            }
#pragma unroll
            for (int nt = 0; nt < NT; nt++) {
                int n = nt * 64 + nw * 8 + g;
                bfr[nt][0] = *(const uint32_t*)&Bsh[n * MS_SBH + k0 + 2 * tg];
                bfr[nt][1] = *(const uint32_t*)&Bsh[n * MS_SBH + k0 + 2 * tg + 8];
            }
#pragma unroll
            for (int mt = 0; mt < 4; mt++)
#pragma unroll
                for (int nt = 0; nt < NT; nt++)
                    mma_f16(acc[mt][nt], afr[mt], bfr[nt]);
        }

        float rp[4][2];
#pragma unroll
        for (int mt = 0; mt < 4; mt++) { rp[mt][0] = -INFINITY; rp[mt][1] = -INFINITY; }
#pragma unroll
        for (int nt = 0; nt < NT; nt++)
#pragma unroll
            for (int mt = 0; mt < 4; mt++)
#pragma unroll
                for (int k = 0; k < 4; k++) {
                    int j = nt * 64 + nw * 8 + 2 * tg + (k & 1);
                    if (j < nc) rp[mt][k >> 1] = fmaxf(rp[mt][k >> 1], acc[mt][nt][k]);
                }
#pragma unroll
        for (int off = 1; off <= 2; off <<= 1)
#pragma unroll
            for (int mt = 0; mt < 4; mt++)
#pragma unroll
                for (int h = 0; h < 2; h++)
                    rp[mt][h] = fmaxf(rp[mt][h], __shfl_xor_sync(0xffffffffu, rp[mt][h], off));
        if (tg == 0) {
#pragma unroll
            for (int mt = 0; mt < 4; mt++)
#pragma unroll
                for (int h = 0; h < 2; h++)
                    red[nw * 128 + m_warp + mt * 16 + g + 8 * h] = rp[mt][h];
        }
        __syncthreads();

        if (i < 3 && tt + 1 < ntiles) {
            MS_STAGEA(tt + 1);
            CP_COMMIT();
        }

        if (t < 128) {
            float mx = red[t];
#pragma unroll
            for (int r8 = 1; r8 < 8; r8++) mx = fmaxf(mx, red[r8 * 128 + t]);
            rowmax[t] = mx;
        }
        __syncthreads();

        if (t < 64) {
            int qs = g_tile_qs[tt], qe = g_tile_qe[tt];
            int qi = qs + t;
            if (qi < qe) {
                int rs = g_tile_rs[tt];
                int r0 = g_qoff[qi] - rs;
                int r1 = g_qoff[qi + 1] - rs;
                float s = 0.f;
                for (int r = r0; r < r1; r++) s += rowmax[r];
                float nu = g_denom[qi];
                out[qi * CC + c] = ((31.f - nu) * g_cmax[c] + s) / nu;
            }
        }
        __syncthreads();
    }
}

__global__ __launch_bounds__(512, 1) void maxsim_kernel(float* __restrict__ out) {
    // Reset the ticket counter so the NEXT kernel_launch invocation starts at 0.
    // (proj has already consumed g_nun earlier in this sequence.)
    if (blockIdx.x == 0 && blockIdx.y == 0 && threadIdx.x == 0) g_nun = 0;

    extern __shared__ char smc[];
    __half* Ash   = (__half*)smc;
    __half* Bsh   = Ash + MSA_HALFS;
    float* red    = (float*)(Bsh + MSB_HALFS);
    float* rowmax = red + 8 * 128;
    int*   sidx   = (int*)(rowmax + 128);

    int t  = threadIdx.x;
    int c  = blockIdx.x;
    int yy = blockIdx.y;

    int ntiles = g_ntiles;
    if (yy * 4 >= ntiles) return;

    int nc = g_cnt[c];
    int NT = (nc + 63) >> 6;

    if (t < 256) sidx[t] = g_idx[c * 256 + t];
    __syncthreads();

    {
        const __half* base = g_colh + (size_t)(QROWS + c * CT) * D;
        int chunks = nc * 16;
#pragma unroll
        for (int j = 0; j < 8; j++) {
            int idx = t + j * 512;
            if (idx < chunks) {
                int n = idx >> 4, k8 = idx & 15;
                CP_ASYNC16(smem_u32(&Bsh[n * MS_SBH + k8 * 8]),
                           base + (size_t)sidx[n] * D + k8 * 8);
            }
        }
    }
    CP_COMMIT();

    MS_STAGEA(yy * 4);
    CP_COMMIT();

    if (NT == 2)      ms_body<2>(Ash, Bsh, red, rowmax, out, t, c, yy, nc, ntiles);
    else if (NT == 3) ms_body<3>(Ash, Bsh, red, rowmax, out, t, c, yy, nc, ntiles);
    else if (NT == 1) ms_body<1>(Ash, Bsh, red, rowmax, out, t, c, yy, nc, ntiles);
    else              ms_body<4>(Ash, Bsh, red, rowmax, out, t, c, yy, nc, ntiles);
}

// ---------------------------------------------------------------------------
extern "C" void kernel_launch(void* const* d_in, const int* in_sizes, int n_in,
                              void* d_out, int out_size) {
    const float* qh  = (const float*)d_in[0];
    const float* ch  = (const float*)d_in[1];
    const float* Wm  = (const float*)d_in[2];
    const float* bia = (const float*)d_in[3];
    const int*   qm  = (const int*)d_in[4];
    const int*   cm  = (const int*)d_in[5];
    float* out = (float*)d_out;

    cudaFuncSetAttribute(proj_kernel,
                         cudaFuncAttributeMaxDynamicSharedMemorySize,
                         P_SMEM_BYTES);
    cudaFuncSetAttribute(maxsim_kernel,
                         cudaFuncAttributeMaxDynamicSharedMemorySize,
                         MS_SMEM_BYTES);

    setup_kernel<<<320, 256>>>(qh, ch, bia, qm, cm, out);
    proj_kernel<<<(NROWS + 127) / 128, 256, P_SMEM_BYTES>>>(qh, ch, Wm, bia);
    cmax_kernel<<<CC, 256>>>(bia);
    maxsim_kernel<<<dim3(CC, 4), 512, MS_SMEM_BYTES>>>(out);
}